// round 1
// baseline (speedup 1.0000x reference)
#include <cuda_runtime.h>

#define R_ 8
#define K_ 10
#define D_ 256
#define DL_ 10
#define B_ 4096
#define J_ 100          // K_*DL_
#define TB 56           // rows per CTA tile (8 warps x 7 rows)
#define NTILE 74        // ceil(4096/56)
#define USTR 260        // padded row stride for Usm[j][*] (1040B: 16B aligned, odd/16 -> conflict-free)
#define TEMP_INV 10.0f  // 1/0.1

#define GSZ (K_ * DL_ * DL_)    // 1000 floats per r

// Gram matrices G[r][k] = U_rk^T U_rk  (10x10 each)
__device__ float g_G[R_ * GSZ];

// ---------- packed f32x2 helpers (Blackwell FFMA2) ----------
__device__ __forceinline__ void fma2(unsigned long long &acc,
                                     unsigned long long a,
                                     unsigned long long b) {
    asm("fma.rn.f32x2 %0, %1, %2, %0;" : "+l"(acc) : "l"(a), "l"(b));
}
__device__ __forceinline__ unsigned long long pack2(float v) {
    unsigned long long r;
    unsigned int u = __float_as_uint(v);
    asm("mov.b64 %0, {%1, %1};" : "=l"(r) : "r"(u));
    return r;
}
__device__ __forceinline__ float2 unpack2(unsigned long long v) {
    unsigned int lo, hi;
    asm("mov.b64 {%0, %1}, %2;" : "=r"(lo), "=r"(hi) : "l"(v));
    return make_float2(__uint_as_float(lo), __uint_as_float(hi));
}

// ---------- kernel 1: Gram matrices ----------
__global__ void ks_gram(const float* __restrict__ Us) {
    __shared__ float u[D_ * DL_];   // 2560 floats, layout [Dd][d]
    const int rk = blockIdx.x;      // 0..79
    const float* Up = Us + (size_t)rk * D_ * DL_;
    for (int i = threadIdx.x; i < D_ * DL_; i += blockDim.x) u[i] = Up[i];
    __syncthreads();
    const int t = threadIdx.x;
    if (t < DL_ * DL_) {
        const int i = t / DL_, j = t % DL_;
        float s = 0.0f;
        #pragma unroll 8
        for (int Dd = 0; Dd < D_; Dd++)
            s += u[Dd * DL_ + i] * u[Dd * DL_ + j];
        g_G[rk * (DL_ * DL_) + t] = s;
    }
}

// ---------- smem layout (floats) ----------
#define OFF_XS 0
#define OFF_U  (OFF_XS + TB * D_)          // 14336
#define OFF_ZW (OFF_U + J_ * USTR)         // +26000
#define OFF_LG (OFF_ZW + TB * J_)          // +5600
#define OFF_G  (OFF_LG + TB * K_)          // +560
#define SMEM_FLOATS (OFF_G + GSZ)          // +1000 = 47496 floats = 189984 B

// ---------- kernel 2: fused main ----------
extern "C" __global__ void __launch_bounds__(256, 1)
ks_main(const float* __restrict__ x, const float* __restrict__ Us,
        float* __restrict__ out) {
    extern __shared__ float sm[];
    float* xs  = sm + OFF_XS;   // [TB][256]
    float* Usm = sm + OFF_U;    // [100][USTR]  (j-major: Usm[j][Dd])
    float* zw  = sm + OFF_ZW;   // [TB][100]    z, then w = c*z in place
    float* lg  = sm + OFF_LG;   // [TB][10]     softmax logits
    float* Gs  = sm + OFF_G;    // [10][10][10]

    const int tid  = threadIdx.x;
    const int tile = blockIdx.x;
    const int r    = blockIdx.y;
    const int b0   = tile * TB;

    // ---- load x tile (row-clamped so partial tiles need no compute guards) ----
    for (int i = tid; i < TB * (D_ / 4); i += 256) {
        const int row = i / (D_ / 4), c4 = i % (D_ / 4);
        const int gb = min(b0 + row, B_ - 1);
        ((float4*)xs)[row * (D_ / 4) + c4] =
            ((const float4*)x)[(size_t)gb * (D_ / 4) + c4];
    }
    // ---- load U_r into j-major smem (global reads fully coalesced) ----
    {
        const float* Ur = Us + (size_t)r * (K_ * D_ * DL_);
        for (int i = tid; i < K_ * D_ * DL_; i += 256) {
            const float v = Ur[i];
            const int d  = i % DL_;
            const int Dd = (i / DL_) % D_;
            const int k  = i / (D_ * DL_);
            Usm[(k * DL_ + d) * USTR + Dd] = v;
        }
    }
    for (int i = tid; i < GSZ; i += 256) Gs[i] = g_G[r * GSZ + i];
    __syncthreads();

    const int w  = tid >> 5;
    const int ln = tid & 31;
    const int rb = w * 7;    // this warp's first row (8 warps x 7 rows = 56)

    // ================= phase 1: z = x @ Ucat  (TBx256 @ 256x100) =================
    {
        const int j0 = ln, j1 = ln + 32, j2 = ln + 64;
        const int j3 = (ln < 4) ? (96 + ln) : ln;   // dummy duplicate for ln>=4

        unsigned long long acc[7][4];
        #pragma unroll
        for (int rr = 0; rr < 7; rr++)
            #pragma unroll
            for (int s = 0; s < 4; s++) acc[rr][s] = 0ULL;

        const ulonglong2* u0p = (const ulonglong2*)(Usm + j0 * USTR);
        const ulonglong2* u1p = (const ulonglong2*)(Usm + j1 * USTR);
        const ulonglong2* u2p = (const ulonglong2*)(Usm + j2 * USTR);
        const ulonglong2* u3p = (const ulonglong2*)(Usm + j3 * USTR);

        for (int Dq = 0; Dq < D_ / 4; Dq++) {
            const ulonglong2 u0 = u0p[Dq];
            const ulonglong2 u1 = u1p[Dq];
            const ulonglong2 u2 = u2p[Dq];
            const ulonglong2 u3 = u3p[Dq];
            #pragma unroll
            for (int rr = 0; rr < 7; rr++) {
                const ulonglong2 xv =
                    ((const ulonglong2*)(xs + (rb + rr) * D_))[Dq];
                fma2(acc[rr][0], u0.x, xv.x); fma2(acc[rr][0], u0.y, xv.y);
                fma2(acc[rr][1], u1.x, xv.x); fma2(acc[rr][1], u1.y, xv.y);
                fma2(acc[rr][2], u2.x, xv.x); fma2(acc[rr][2], u2.y, xv.y);
                fma2(acc[rr][3], u3.x, xv.x); fma2(acc[rr][3], u3.y, xv.y);
            }
        }
        #pragma unroll
        for (int rr = 0; rr < 7; rr++) {
            const int b = rb + rr;
            float2 v;
            v = unpack2(acc[rr][0]); zw[b * J_ + j0] = v.x + v.y;
            v = unpack2(acc[rr][1]); zw[b * J_ + j1] = v.x + v.y;
            v = unpack2(acc[rr][2]); zw[b * J_ + j2] = v.x + v.y;
            if (ln < 4) { v = unpack2(acc[rr][3]); zw[b * J_ + 96 + ln] = v.x + v.y; }
        }
    }
    __syncthreads();

    // ====== phase 2a: logits a_k = (|z_k|^2 - 0.5 z^T G z) / T  (constant cancels) ======
    for (int t = tid; t < TB * K_; t += 256) {
        const int b = t / K_, k = t - b * K_;
        const float* zb = zw + b * J_ + k * DL_;
        float z[DL_];
        #pragma unroll
        for (int i = 0; i < DL_; i++) z[i] = zb[i];
        float s1 = 0.0f;
        #pragma unroll
        for (int i = 0; i < DL_; i++) s1 += z[i] * z[i];
        const float* Gk = Gs + k * (DL_ * DL_);
        float s2 = 0.0f;
        #pragma unroll
        for (int i = 0; i < DL_; i++) {
            float gi = 0.0f;
            #pragma unroll
            for (int jj = 0; jj < DL_; jj++) gi += Gk[i * DL_ + jj] * z[jj];
            s2 += gi * z[i];
        }
        lg[t] = (s1 - 0.5f * s2) * TEMP_INV;
    }
    __syncthreads();

    // ====== phase 2b: softmax over k, w = c * z in place ======
    for (int t = tid; t < TB * K_; t += 256) {
        const int b = t / K_, k = t - b * K_;
        float a[K_], m = -1e30f;
        #pragma unroll
        for (int kk = 0; kk < K_; kk++) { a[kk] = lg[b * K_ + kk]; m = fmaxf(m, a[kk]); }
        float s = 0.0f, ek = 0.0f;
        #pragma unroll
        for (int kk = 0; kk < K_; kk++) {
            const float e = expf(a[kk] - m);
            s += e;
            if (kk == k) ek = e;
        }
        const float c = ek / s;
        #pragma unroll
        for (int d = 0; d < DL_; d++) zw[b * J_ + k * DL_ + d] *= c;
    }
    __syncthreads();

    // ================= phase 3: out = W @ Ucat^T  (TBx100 @ 100x256) =================
    {
        unsigned long long acc[7][4];
        #pragma unroll
        for (int rr = 0; rr < 7; rr++)
            #pragma unroll
            for (int s = 0; s < 4; s++) acc[rr][s] = 0ULL;

        // lane owns dd pairs {2*ln + 64*t, 2*ln + 64*t + 1}, t=0..3
        for (int j = 0; j < J_; j++) {
            const unsigned long long* up =
                (const unsigned long long*)(Usm + j * USTR);
            unsigned long long u[4];
            #pragma unroll
            for (int t = 0; t < 4; t++) u[t] = up[ln + 32 * t];
            #pragma unroll
            for (int rr = 0; rr < 7; rr++) {
                const unsigned long long w2 = pack2(zw[(rb + rr) * J_ + j]);
                fma2(acc[rr][0], u[0], w2);
                fma2(acc[rr][1], u[1], w2);
                fma2(acc[rr][2], u[2], w2);
                fma2(acc[rr][3], u[3], w2);
            }
        }
        #pragma unroll
        for (int rr = 0; rr < 7; rr++) {
            const int gb = b0 + rb + rr;
            if (gb < B_) {
                float* op = out + ((size_t)r * B_ + gb) * D_;
                #pragma unroll
                for (int t = 0; t < 4; t++) {
                    const float2 v = unpack2(acc[rr][t]);
                    ((float2*)op)[ln + 32 * t] = v;
                }
            }
        }
    }
}

extern "C" void kernel_launch(void* const* d_in, const int* in_sizes, int n_in,
                              void* d_out, int out_size) {
    const float* x  = (const float*)d_in[0];   // (4096, 256)
    const float* Us = (const float*)d_in[1];   // (8, 10, 256, 10)
    float* out = (float*)d_out;                // (8, 4096, 256)

    cudaFuncSetAttribute(ks_main, cudaFuncAttributeMaxDynamicSharedMemorySize,
                         SMEM_FLOATS * 4);

    ks_gram<<<R_ * K_, 128>>>(Us);
    dim3 grid(NTILE, R_);
    ks_main<<<grid, 256, SMEM_FLOATS * 4>>>(x, Us, out);
}

// round 3
// speedup vs baseline: 1.4547x; 1.4547x over previous
#include <cuda_runtime.h>

#define R_ 8
#define K_ 10
#define D_ 256
#define DL_ 10
#define B_ 4096
#define MT 64            // rows per CTA
#define ZSTR 108         // zw row stride (floats)
#define OSTR 260         // epilogue bounce stride (floats)

// ---------------- smem layout (bytes) ----------------
#define SM_A   0                         // 64 rows x 1024B (x, tf32)   | phase2: 64 x 512B (w)
#define SM_U   65536                     // 25600 fp32 raw U (tf32-converted), 102400B
#define SM_ZW  167936                    // 64 x 108 x 4 = 27648
#define SM_GP  195584                    // 560 x 4 = 2240
#define SM_LG  197824                    // 640 x 4 = 2560
#define SM_LG2 200384                    // 640 x 4 = 2560
#define SMEM_TOTAL 202944

// packed symmetric Gram: P[r][k][t], t over (i<=j), diag x1, off-diag x2
__device__ float g_P[R_ * K_ * 56];

__device__ __forceinline__ unsigned tf32b(float f) {
    unsigned u;
    asm("cvt.rna.tf32.f32 %0, %1;" : "=r"(u) : "f"(f));
    return u;
}

__device__ __forceinline__ void mma8(float* c, unsigned a0, unsigned a1,
                                     unsigned a2, unsigned a3,
                                     unsigned b0, unsigned b1) {
    asm volatile(
        "mma.sync.aligned.m16n8k8.row.col.f32.tf32.tf32.f32 "
        "{%0,%1,%2,%3}, {%4,%5,%6,%7}, {%8,%9}, {%0,%1,%2,%3};"
        : "+f"(c[0]), "+f"(c[1]), "+f"(c[2]), "+f"(c[3])
        : "r"(a0), "r"(a1), "r"(a2), "r"(a3), "r"(b0), "r"(b1));
}

// ---------------- kernel 1: packed symmetric Gram ----------------
__global__ void ks_gram(const float* __restrict__ Us) {
    __shared__ float u[D_ * DL_];
    __shared__ float G[DL_ * DL_];
    const int rk = blockIdx.x;
    const float* Up = Us + (size_t)rk * D_ * DL_;
    for (int i = threadIdx.x; i < D_ * DL_; i += 128) u[i] = Up[i];
    __syncthreads();
    const int t = threadIdx.x;
    if (t < DL_ * DL_) {
        const int i = t / DL_, j = t % DL_;
        float s = 0.0f;
        #pragma unroll 8
        for (int dd = 0; dd < D_; dd++) s += u[dd * DL_ + i] * u[dd * DL_ + j];
        G[t] = s;
    }
    __syncthreads();
    if (t < 55) {
        int tt = t, i = 0;
        while (tt >= DL_ - i) { tt -= DL_ - i; i++; }
        const int j = i + tt;
        g_P[rk * 56 + t] = G[i * DL_ + j] * (i == j ? 1.0f : 2.0f);
    }
}

// ---------------- kernel 2: fused mma.sync tf32 main ----------------
extern "C" __global__ void __launch_bounds__(256, 1)
ks_main(const float* __restrict__ x, const float* __restrict__ Us,
        float* __restrict__ out) {
    extern __shared__ __align__(128) char smem[];
    const int tid = threadIdx.x, wid = tid >> 5, lane = tid & 31;
    const int g = lane >> 2, tig = lane & 3;
    const int r = blockIdx.y, b0 = blockIdx.x * MT;
    const int mw = wid >> 2;      // 0..1  (m-group of 32 rows)
    const int nw = wid & 3;       // 0..3  (n-group)
    const unsigned sxb = (unsigned)((g & 1) << 6);

    const float* Up = (const float*)(smem + SM_U);
    float* ZW = (float*)(smem + SM_ZW);
    float* GP = (float*)(smem + SM_GP);
    float* LG = (float*)(smem + SM_LG);
    float* LG2 = (float*)(smem + SM_LG2);

    // ======== staging: Gram, x (tf32, swizzled), U (tf32, raw order) ========
    for (int i = tid; i < 560; i += 256) GP[i] = g_P[r * 560 + i];
    for (int i = tid; i < MT * 64; i += 256) {       // x: 64 rows x 64 float4
        const int row = i >> 6, c4 = i & 63;
        const float4 v = *(const float4*)(x + (size_t)(b0 + row) * D_ + c4 * 4);
        uint4 w;
        w.x = tf32b(v.x); w.y = tf32b(v.y); w.z = tf32b(v.z); w.w = tf32b(v.w);
        *(uint4*)(smem + SM_A + row * 1024 + ((unsigned)(c4 * 16) ^ ((unsigned)(row & 1) << 6))) = w;
    }
    {
        const float* Ur = Us + (size_t)r * (K_ * D_ * DL_);
        for (int i = tid; i < 6400; i += 256) {      // 25600 floats as float4
            const float4 v = *(const float4*)(Ur + i * 4);
            uint4 w;
            w.x = tf32b(v.x); w.y = tf32b(v.y); w.z = tf32b(v.z); w.w = tf32b(v.w);
            *(uint4*)(smem + SM_U + i * 16) = w;
        }
    }
    __syncthreads();

    // ======== phase 1: z[64][100] = x[64][256] @ Ucat[256][100] ========
    {
        // n-tile setup (13 tiles of 8 cols; warp nw takes tiles nw, nw+4, nw+8, nw+12)
        int jof[4]; unsigned jval[4]; int tvalid[4];
        #pragma unroll
        for (int nt = 0; nt < 4; nt++) {
            const int tile = nw + 4 * nt;
            const int j = tile * 8 + g;
            const bool v = (tile <= 12) && (j < 100);
            jof[nt] = v ? ((j / 10) * 2560 + (j % 10)) : 0;
            jval[nt] = v ? 1u : 0u;
            tvalid[nt] = (tile <= 12);
        }
        const char* Ar[2][2];
        #pragma unroll
        for (int mt = 0; mt < 2; mt++)
            #pragma unroll
            for (int h = 0; h < 2; h++)
                Ar[mt][h] = smem + SM_A + (mw * 32 + mt * 16 + g + 8 * h) * 1024;

        float acc[2][4][4];
        #pragma unroll
        for (int mt = 0; mt < 2; mt++)
            #pragma unroll
            for (int nt = 0; nt < 4; nt++)
                #pragma unroll
                for (int q = 0; q < 4; q++) acc[mt][nt][q] = 0.0f;

        for (int kb = 0; kb < 16; kb++) {
            const unsigned ka = ((unsigned)(kb * 64 + tig * 16)) ^ sxb;
            uint4 a[2][2];
            #pragma unroll
            for (int mt = 0; mt < 2; mt++)
                #pragma unroll
                for (int h = 0; h < 2; h++)
                    a[mt][h] = *(const uint4*)(Ar[mt][h] + ka);
            #pragma unroll
            for (int nt = 0; nt < 4; nt++) {
                const int bi = jof[nt] + (kb * 16 + 4 * tig) * 10;
                unsigned b0 = 0, b1 = 0, b2 = 0, b3 = 0;
                if (jval[nt]) {
                    b0 = __float_as_uint(Up[bi]);
                    b1 = __float_as_uint(Up[bi + 10]);
                    b2 = __float_as_uint(Up[bi + 20]);
                    b3 = __float_as_uint(Up[bi + 30]);
                }
                #pragma unroll
                for (int mt = 0; mt < 2; mt++) {
                    mma8(acc[mt][nt], a[mt][0].x, a[mt][1].x, a[mt][0].y, a[mt][1].y, b0, b1);
                    mma8(acc[mt][nt], a[mt][0].z, a[mt][1].z, a[mt][0].w, a[mt][1].w, b2, b3);
                }
            }
        }
        // write z fragments to zw
        #pragma unroll
        for (int mt = 0; mt < 2; mt++)
            #pragma unroll
            for (int nt = 0; nt < 4; nt++)
                if (tvalid[nt]) {
                    const int col = (nw + 4 * nt) * 8 + 2 * tig;
                    const int r0 = mw * 32 + mt * 16 + g;
                    *(float2*)(ZW + r0 * ZSTR + col) = make_float2(acc[mt][nt][0], acc[mt][nt][1]);
                    *(float2*)(ZW + (r0 + 8) * ZSTR + col) = make_float2(acc[mt][nt][2], acc[mt][nt][3]);
                }
    }
    __syncthreads();

    // ======== phase 2a: logits = 10|z_k|^2 - 5 z_k^T G_k z_k ========
    for (int t = tid; t < MT * K_; t += 256) {
        const int row = t / 10, k = t - row * 10;
        const float* zb = ZW + row * ZSTR + k * 10;
        float z[DL_];
        #pragma unroll
        for (int i = 0; i < DL_; i++) z[i] = zb[i];
        float s1 = 0.0f;
        #pragma unroll
        for (int i = 0; i < DL_; i++) s1 += z[i] * z[i];
        const float* Pk = GP + k * 56;
        float s2 = 0.0f; int tt = 0;
        #pragma unroll
        for (int i = 0; i < DL_; i++)
            #pragma unroll
            for (int j = i; j < DL_; j++) { s2 += Pk[tt] * z[i] * z[j]; tt++; }
        LG[t] = 10.0f * s1 - 5.0f * s2;
    }
    __syncthreads();

    // ======== phase 2b: softmax probs ========
    for (int t = tid; t < MT * K_; t += 256) {
        const int row = t / 10, k = t - row * 10;
        float a[K_], m = -1e30f;
        #pragma unroll
        for (int kk = 0; kk < K_; kk++) { a[kk] = LG[row * 10 + kk]; m = fmaxf(m, a[kk]); }
        float s = 0.0f, ek = 0.0f;
        #pragma unroll
        for (int kk = 0; kk < K_; kk++) {
            const float e = expf(a[kk] - m);
            s += e;
            if (kk == k) ek = e;
        }
        LG2[t] = ek / s;
    }
    __syncthreads();

    // ======== phase 2c: w = c*z -> A2 (64 rows x 512B, tf32, swizzled) ========
    for (int t = tid; t < MT * 100; t += 256) {
        const int row = t / 100, j = t - row * 100;
        const float wv = LG2[row * 10 + j / 10] * ZW[row * ZSTR + j];
        *(unsigned*)(smem + SM_A + row * 512 + (((unsigned)(j * 4)) ^ ((unsigned)(row & 1) << 6))) = tf32b(wv);
    }
    for (int t = tid; t < MT * 28; t += 256) {       // zero pad cols 100..127
        const int row = t / 28, j = 100 + (t - row * 28);
        *(unsigned*)(smem + SM_A + row * 512 + (((unsigned)(j * 4)) ^ ((unsigned)(row & 1) << 6))) = 0u;
    }
    __syncthreads();

    // ======== phase 3: out[64][256] = w[64][128] @ Ucat^T[128][256] ========
    float acc2[2][8][4];
    {
        #pragma unroll
        for (int mt = 0; mt < 2; mt++)
            #pragma unroll
            for (int nt = 0; nt < 8; nt++)
                #pragma unroll
                for (int q = 0; q < 4; q++) acc2[mt][nt][q] = 0.0f;

        const char* Ar[2][2];
        #pragma unroll
        for (int mt = 0; mt < 2; mt++)
            #pragma unroll
            for (int h = 0; h < 2; h++)
                Ar[mt][h] = smem + SM_A + (mw * 32 + mt * 16 + g + 8 * h) * 512;

        for (int kb = 0; kb < 7; kb++) {
            const unsigned ka = ((unsigned)(kb * 64 + tig * 16)) ^ sxb;
            uint4 a[2][2];
            #pragma unroll
            for (int mt = 0; mt < 2; mt++)
                #pragma unroll
                for (int h = 0; h < 2; h++)
                    a[mt][h] = *(const uint4*)(Ar[mt][h] + ka);

            int jbase[4]; unsigned jv[4];
            #pragma unroll
            for (int pos = 0; pos < 4; pos++) {
                const int j = kb * 16 + 4 * tig + pos;
                jv[pos] = (j < 100) ? 1u : 0u;
                jbase[pos] = (j / 10) * 2560 + (j % 10);
            }
            #pragma unroll
            for (int nt = 0; nt < 8; nt++) {
                const int ddb = ((nw * 8 + nt) * 8 + g) * 10;
                unsigned b[4];
                #pragma unroll
                for (int pos = 0; pos < 4; pos++)
                    b[pos] = jv[pos] ? __float_as_uint(Up[jbase[pos] + ddb]) : 0u;
                #pragma unroll
                for (int mt = 0; mt < 2; mt++) {
                    mma8(acc2[mt][nt], a[mt][0].x, a[mt][1].x, a[mt][0].y, a[mt][1].y, b[0], b[1]);
                    mma8(acc2[mt][nt], a[mt][0].z, a[mt][1].z, a[mt][0].w, a[mt][1].w, b[2], b[3]);
                }
            }
        }
    }
    __syncthreads();   // all smem reads done; reuse as epilogue bounce

    // ======== epilogue: frags -> smem bounce -> coalesced STG ========
    float* OB = (float*)smem;
    #pragma unroll
    for (int mt = 0; mt < 2; mt++)
        #pragma unroll
        for (int nt = 0; nt < 8; nt++) {
            const int col = (nw * 8 + nt) * 8 + 2 * tig;
            const int r0 = mw * 32 + mt * 16 + g;
            *(float2*)(OB + r0 * OSTR + col) = make_float2(acc2[mt][nt][0], acc2[mt][nt][1]);
            *(float2*)(OB + (r0 + 8) * OSTR + col) = make_float2(acc2[mt][nt][2], acc2[mt][nt][3]);
        }
    __syncthreads();
    for (int i = tid; i < MT * 64; i += 256) {
        const int row = i >> 6, c4 = i & 63;
        const float4 v = *(const float4*)(OB + row * OSTR + c4 * 4);
        *(float4*)(out + ((size_t)r * B_ + b0 + row) * D_ + c4 * 4) = v;
    }
}

extern "C" void kernel_launch(void* const* d_in, const int* in_sizes, int n_in,
                              void* d_out, int out_size) {
    const float* x  = (const float*)d_in[0];   // (4096, 256)
    const float* Us = (const float*)d_in[1];   // (8, 10, 256, 10)
    float* out = (float*)d_out;                // (8, 4096, 256)

    cudaFuncSetAttribute(ks_main, cudaFuncAttributeMaxDynamicSharedMemorySize,
                         SMEM_TOTAL);
    ks_gram<<<R_ * K_, 128>>>(Us);
    dim3 grid(B_ / MT, R_);
    ks_main<<<grid, 256, SMEM_TOTAL>>>(x, Us, out);
}

// round 4
// speedup vs baseline: 1.5915x; 1.0940x over previous
#include <cuda_runtime.h>

#define R_ 8
#define K_ 10
#define D_ 256
#define DL_ 10
#define B_ 4096
#define MT 64
#define NT_ 64          // number of row tiles = B_/MT
#define ZSTR 104
#define OSTR 260

// ---------------- device scratch (static, no allocs) ----------------
__device__ float    g_P[R_ * K_ * 56];                 // packed symmetric Gram
__device__ unsigned g_xp[NT_ * 16 * 4 * 64 * 4];       // x tf32 frag-order [tile][kb][tig][row]{4k}  (4MB)
__device__ unsigned g_u1[R_ * 13 * 16 * 32 * 4];       // GEMM1 B frags [r][tile13][kb16][lane]{4k}   (1MB)
__device__ unsigned g_u2[R_ * 32 * 7 * 32 * 4];        // GEMM2 B frags [r][tileN32][kb7][lane]{4j}   (0.9MB)

__device__ __forceinline__ unsigned tf32b(float f) {
    unsigned u;
    asm("cvt.rna.tf32.f32 %0, %1;" : "=r"(u) : "f"(f));
    return u;
}
__device__ __forceinline__ void mma8(float* c, unsigned a0, unsigned a1,
                                     unsigned a2, unsigned a3,
                                     unsigned b0, unsigned b1) {
    asm volatile(
        "mma.sync.aligned.m16n8k8.row.col.f32.tf32.tf32.f32 "
        "{%0,%1,%2,%3}, {%4,%5,%6,%7}, {%8,%9}, {%0,%1,%2,%3};"
        : "+f"(c[0]), "+f"(c[1]), "+f"(c[2]), "+f"(c[3])
        : "r"(a0), "r"(a1), "r"(a2), "r"(a3), "r"(b0), "r"(b1));
}

// ---------------- prep: packed symmetric Gram ----------------
__global__ void ks_gram(const float* __restrict__ Us) {
    __shared__ float u[D_ * DL_];
    __shared__ float G[DL_ * DL_];
    const int rk = blockIdx.x;
    const float* Up = Us + (size_t)rk * D_ * DL_;
    for (int i = threadIdx.x; i < D_ * DL_; i += 128) u[i] = Up[i];
    __syncthreads();
    const int t = threadIdx.x;
    if (t < DL_ * DL_) {
        const int i = t / DL_, j = t % DL_;
        float s = 0.0f;
        #pragma unroll 8
        for (int dd = 0; dd < D_; dd++) s += u[dd * DL_ + i] * u[dd * DL_ + j];
        G[t] = s;
    }
    __syncthreads();
    if (t < 55) {
        int tt = t, i = 0;
        while (tt >= DL_ - i) { tt -= DL_ - i; i++; }
        const int j = i + tt;
        g_P[rk * 56 + t] = G[i * DL_ + j] * (i == j ? 1.0f : 2.0f);
    }
}

// ---------------- prep: x -> tf32 fragment order ----------------
__global__ void ks_xpack(const float* __restrict__ x) {
    const int tile = blockIdx.x;
    for (int e = threadIdx.x; e < 4096; e += 256) {
        const int row = e & 63, kt = e >> 6;
        const int k0 = (kt >> 2) * 16 + (kt & 3) * 4;
        const float* xp = x + (size_t)(tile * 64 + row) * D_ + k0;
        uint4 v;
        v.x = tf32b(xp[0]); v.y = tf32b(xp[1]);
        v.z = tf32b(xp[2]); v.w = tf32b(xp[3]);
        ((uint4*)g_xp)[(size_t)tile * 4096 + e] = v;
    }
}

// ---------------- prep: U -> GEMM1 B fragments ----------------
__global__ void ks_upack1(const float* __restrict__ Us) {
    const int r = blockIdx.x / 13, tile = blockIdx.x % 13;
    const int e = threadIdx.x;             // 512 entries: kb*32+lane
    const int lane = e & 31, kb = e >> 5;
    const int g = lane >> 2, tig = lane & 3;
    const int j = tile * 8 + g, k0 = kb * 16 + tig * 4;
    uint4 v = make_uint4(0u, 0u, 0u, 0u);
    if (j < 100) {
        const float* up = Us + ((size_t)(r * 10 + j / 10) * D_ + k0) * 10 + (j % 10);
        v.x = tf32b(up[0]);  v.y = tf32b(up[10]);
        v.z = tf32b(up[20]); v.w = tf32b(up[30]);
    }
    ((uint4*)g_u1)[((r * 13 + tile) * 16 + kb) * 32 + lane] = v;
}

// ---------------- prep: U -> GEMM2 B fragments ----------------
__global__ void ks_upack2(const float* __restrict__ Us) {
    const int r = blockIdx.x >> 5, tile = blockIdx.x & 31;
    const int e = threadIdx.x;             // 224 entries: kb*32+lane
    const int lane = e & 31, kb = e >> 5;
    const int g = lane >> 2, tig = lane & 3;
    const int dd = tile * 8 + g, j0 = kb * 16 + tig * 4;
    unsigned w[4];
    #pragma unroll
    for (int q = 0; q < 4; q++) {
        const int j = j0 + q;
        w[q] = (j < 100)
            ? tf32b(Us[((size_t)(r * 10 + j / 10) * D_ + dd) * 10 + (j % 10)])
            : 0u;
    }
    ((uint4*)g_u2)[((r * 32 + tile) * 7 + kb) * 32 + lane] =
        make_uint4(w[0], w[1], w[2], w[3]);
}

// ---------------- smem layout (bytes) ----------------
#define SM_W   0          // 64 x 512B  w fragments (phase-2 A operand)
#define SM_ZW  32768      // 64 x 104 x 4 = 26624
#define SM_GP  59392      // 2240
#define SM_LG  61632      // 2560
#define SM_LG2 64192      // 2560
#define SMEM_TOTAL 66752  // epilogue bounce (64 x 260 x 4 = 66560) overlays from 0

// ---------------- main fused kernel ----------------
extern "C" __global__ void __launch_bounds__(256, 2)
ks_main(float* __restrict__ out) {
    extern __shared__ __align__(128) char smem[];
    const int tid = threadIdx.x, wid = tid >> 5, lane = tid & 31;
    const int g = lane >> 2, tig = lane & 3;
    const int r = blockIdx.y, tile = blockIdx.x, b0 = tile * MT;
    const int mw = wid >> 2, nw = wid & 3;
    const unsigned sxb = (unsigned)((g & 1) << 6);

    float* ZW  = (float*)(smem + SM_ZW);
    float* GP  = (float*)(smem + SM_GP);
    float* LG  = (float*)(smem + SM_LG);
    float* LG2 = (float*)(smem + SM_LG2);

    for (int i = tid; i < 560; i += 256) GP[i] = g_P[r * 560 + i];

    // ======== GEMM1: z[64][100] = x[64][256] @ Ucat  (pure LDG + HMMA) ========
    {
        int tv[4];
        #pragma unroll
        for (int nt = 0; nt < 4; nt++) tv[nt] = (nw + 4 * nt) < 13;

        const uint4* XP = (const uint4*)g_xp + (size_t)tile * 4096;
        const uint4* U1 = (const uint4*)g_u1 + (size_t)r * 13 * 512;

        float acc[2][4][4];
        #pragma unroll
        for (int mt = 0; mt < 2; mt++)
            #pragma unroll
            for (int nt = 0; nt < 4; nt++)
                #pragma unroll
                for (int q = 0; q < 4; q++) acc[mt][nt][q] = 0.0f;

        #pragma unroll 4
        for (int kb = 0; kb < 16; kb++) {
            uint4 a[2][2];
            #pragma unroll
            for (int mt = 0; mt < 2; mt++)
                #pragma unroll
                for (int h = 0; h < 2; h++)
                    a[mt][h] = XP[kb * 256 + tig * 64 + (mw * 32 + mt * 16 + 8 * h + g)];
            #pragma unroll
            for (int nt = 0; nt < 4; nt++) {
                if (!tv[nt]) continue;
                const uint4 b = U1[(nw + 4 * nt) * 512 + kb * 32 + lane];
                #pragma unroll
                for (int mt = 0; mt < 2; mt++) {
                    mma8(acc[mt][nt], a[mt][0].x, a[mt][1].x, a[mt][0].y, a[mt][1].y, b.x, b.y);
                    mma8(acc[mt][nt], a[mt][0].z, a[mt][1].z, a[mt][0].w, a[mt][1].w, b.z, b.w);
                }
            }
        }
        #pragma unroll
        for (int mt = 0; mt < 2; mt++)
            #pragma unroll
            for (int nt = 0; nt < 4; nt++)
                if (tv[nt]) {
                    const int col = (nw + 4 * nt) * 8 + 2 * tig;
                    const int r0 = mw * 32 + mt * 16 + g;
                    *(float2*)(ZW + r0 * ZSTR + col) = make_float2(acc[mt][nt][0], acc[mt][nt][1]);
                    *(float2*)(ZW + (r0 + 8) * ZSTR + col) = make_float2(acc[mt][nt][2], acc[mt][nt][3]);
                }
    }
    __syncthreads();

    // ======== logits = 10|z_k|^2 - 5 z_k^T G_k z_k ========
    for (int t = tid; t < MT * K_; t += 256) {
        const int row = t / 10, k = t - row * 10;
        const float* zb = ZW + row * ZSTR + k * 10;
        float z[DL_];
        #pragma unroll
        for (int i = 0; i < DL_; i++) z[i] = zb[i];
        float s1 = 0.0f;
        #pragma unroll
        for (int i = 0; i < DL_; i++) s1 += z[i] * z[i];
        const float* Pk = GP + k * 56;
        float s2 = 0.0f; int tt = 0;
        #pragma unroll
        for (int i = 0; i < DL_; i++)
            #pragma unroll
            for (int j = i; j < DL_; j++) { s2 += Pk[tt] * z[i] * z[j]; tt++; }
        LG[t] = 10.0f * s1 - 5.0f * s2;
    }
    __syncthreads();

    // ======== softmax probs (one thread per row) ========
    if (tid < MT) {
        const int row = tid;
        float a[K_], m = -1e30f;
        #pragma unroll
        for (int k = 0; k < K_; k++) { a[k] = LG[row * 10 + k]; m = fmaxf(m, a[k]); }
        float s = 0.0f;
        #pragma unroll
        for (int k = 0; k < K_; k++) { a[k] = expf(a[k] - m); s += a[k]; }
        const float inv = 1.0f / s;
        #pragma unroll
        for (int k = 0; k < K_; k++) LG2[row * 10 + k] = a[k] * inv;
    }
    __syncthreads();

    // ======== w = c*z -> tf32 fragment rows (512B, swizzled) ========
    for (int t = tid; t < MT * 100; t += 256) {
        const int row = t / 100, j = t - row * 100;
        const float wv = LG2[row * 10 + j / 10] * ZW[row * ZSTR + j];
        *(unsigned*)(smem + SM_W + row * 512 +
                     (((unsigned)(j * 4)) ^ ((unsigned)(row & 1) << 6))) = tf32b(wv);
    }
    for (int t = tid; t < MT * 12; t += 256) {   // zero-pad cols 100..111
        const int row = t / 12, j = 100 + (t - row * 12);
        *(unsigned*)(smem + SM_W + row * 512 +
                     (((unsigned)(j * 4)) ^ ((unsigned)(row & 1) << 6))) = 0u;
    }
    __syncthreads();

    // ======== GEMM2: out[64][256] = w[64][112] @ Ucat^T ========
    float acc2[2][8][4];
    {
        #pragma unroll
        for (int mt = 0; mt < 2; mt++)
            #pragma unroll
            for (int nt = 0; nt < 8; nt++)
                #pragma unroll
                for (int q = 0; q < 4; q++) acc2[mt][nt][q] = 0.0f;

        const char* Ar[2][2];
        #pragma unroll
        for (int mt = 0; mt < 2; mt++)
            #pragma unroll
            for (int h = 0; h < 2; h++)
                Ar[mt][h] = smem + SM_W + (mw * 32 + mt * 16 + g + 8 * h) * 512;

        const uint4* U2 = (const uint4*)g_u2 + (size_t)r * (32 * 7 * 32);

        #pragma unroll 2
        for (int kb = 0; kb < 7; kb++) {
            const unsigned ka = ((unsigned)(kb * 64 + tig * 16)) ^ sxb;
            uint4 a[2][2];
            #pragma unroll
            for (int mt = 0; mt < 2; mt++)
                #pragma unroll
                for (int h = 0; h < 2; h++)
                    a[mt][h] = *(const uint4*)(Ar[mt][h] + ka);
            #pragma unroll
            for (int nt = 0; nt < 8; nt++) {
                const uint4 b = U2[((nw * 8 + nt) * 7 + kb) * 32 + lane];
                #pragma unroll
                for (int mt = 0; mt < 2; mt++) {
                    mma8(acc2[mt][nt], a[mt][0].x, a[mt][1].x, a[mt][0].y, a[mt][1].y, b.x, b.y);
                    mma8(acc2[mt][nt], a[mt][0].z, a[mt][1].z, a[mt][0].w, a[mt][1].w, b.z, b.w);
                }
            }
        }
    }
    __syncthreads();   // smem reads done; reuse as epilogue bounce

    // ======== epilogue: frags -> smem bounce -> coalesced STG ========
    float* OB = (float*)smem;
    #pragma unroll
    for (int mt = 0; mt < 2; mt++)
        #pragma unroll
        for (int nt = 0; nt < 8; nt++) {
            const int col = (nw * 8 + nt) * 8 + 2 * tig;
            const int r0 = mw * 32 + mt * 16 + g;
            *(float2*)(OB + r0 * OSTR + col) = make_float2(acc2[mt][nt][0], acc2[mt][nt][1]);
            *(float2*)(OB + (r0 + 8) * OSTR + col) = make_float2(acc2[mt][nt][2], acc2[mt][nt][3]);
        }
    __syncthreads();
    for (int i = tid; i < MT * 64; i += 256) {
        const int row = i >> 6, c4 = i & 63;
        const float4 v = *(const float4*)(OB + row * OSTR + c4 * 4);
        *(float4*)(out + ((size_t)r * B_ + b0 + row) * D_ + c4 * 4) = v;
    }
}

extern "C" void kernel_launch(void* const* d_in, const int* in_sizes, int n_in,
                              void* d_out, int out_size) {
    const float* x  = (const float*)d_in[0];   // (4096, 256)
    const float* Us = (const float*)d_in[1];   // (8, 10, 256, 10)
    float* out = (float*)d_out;                // (8, 4096, 256)

    cudaFuncSetAttribute(ks_main, cudaFuncAttributeMaxDynamicSharedMemorySize,
                         SMEM_TOTAL);

    ks_gram<<<R_ * K_, 128>>>(Us);
    ks_xpack<<<NT_, 256>>>(x);
    ks_upack1<<<R_ * 13, 512>>>(Us);
    ks_upack2<<<R_ * 32, 224>>>(Us);

    dim3 grid(NT_, R_);
    ks_main<<<grid, 256, SMEM_TOTAL>>>(out);
}

// round 5
// speedup vs baseline: 1.7470x; 1.0977x over previous
#include <cuda_runtime.h>

#define R_ 8
#define K_ 10
#define D_ 256
#define DL_ 10
#define B_ 4096
#define MT 64
#define NT_ 64          // number of row tiles = B_/MT
#define ZSTR 104
#define OSTR 260

// ---------------- device scratch (static, no allocs) ----------------
__device__ float    g_P[R_ * K_ * 56];                 // packed symmetric Gram
__device__ unsigned g_xp[NT_ * 16 * 4 * 64 * 4];       // x tf32 frag-order [tile][kb][tig][row]{4k}  (4MB)
__device__ unsigned g_u1[R_ * 13 * 16 * 32 * 4];       // GEMM1 B frags [r][tile13][kb16][lane]{4k}   (1MB)
__device__ unsigned g_u2[R_ * 32 * 7 * 32 * 4];        // GEMM2 B frags [r][tileN32][kb7][lane]{4j}   (0.9MB)

__device__ __forceinline__ unsigned tf32b(float f) {
    unsigned u;
    asm("cvt.rna.tf32.f32 %0, %1;" : "=r"(u) : "f"(f));
    return u;
}
__device__ __forceinline__ void mma8(float* c, unsigned a0, unsigned a1,
                                     unsigned a2, unsigned a3,
                                     unsigned b0, unsigned b1) {
    asm volatile(
        "mma.sync.aligned.m16n8k8.row.col.f32.tf32.tf32.f32 "
        "{%0,%1,%2,%3}, {%4,%5,%6,%7}, {%8,%9}, {%0,%1,%2,%3};"
        : "+f"(c[0]), "+f"(c[1]), "+f"(c[2]), "+f"(c[3])
        : "r"(a0), "r"(a1), "r"(a2), "r"(a3), "r"(b0), "r"(b1));
}

// ---------------- fused prep kernel ----------------
// blocks [0,64):   xpack tile = b
// blocks [64,144): gram  rk   = b-64
// blocks [144,248): upack1 idx = b-144  (r*13+tile)
// blocks [248,504): upack2 idx = b-248  (r*32+tile)
__global__ void __launch_bounds__(256)
ks_prep(const float* __restrict__ x, const float* __restrict__ Us) {
    const int b = blockIdx.x, tidb = threadIdx.x;

    if (b < 64) {                       // ---- xpack ----
        const int tile = b;
        for (int e = tidb; e < 4096; e += 256) {
            const int row = e & 63, kt = e >> 6;
            const int k0 = (kt >> 2) * 16 + (kt & 3) * 4;
            const float* xp = x + (size_t)(tile * 64 + row) * D_ + k0;
            uint4 v;
            v.x = tf32b(xp[0]); v.y = tf32b(xp[1]);
            v.z = tf32b(xp[2]); v.w = tf32b(xp[3]);
            ((uint4*)g_xp)[(size_t)tile * 4096 + e] = v;
        }
    } else if (b < 144) {               // ---- gram ----
        __shared__ float u[D_ * DL_];
        __shared__ float G[DL_ * DL_];
        const int rk = b - 64;
        const float* Up = Us + (size_t)rk * D_ * DL_;
        for (int i = tidb; i < D_ * DL_; i += 256) u[i] = Up[i];
        __syncthreads();
        if (tidb < DL_ * DL_) {
            const int i = tidb / DL_, j = tidb % DL_;
            float s = 0.0f;
            #pragma unroll 8
            for (int dd = 0; dd < D_; dd++) s += u[dd * DL_ + i] * u[dd * DL_ + j];
            G[tidb] = s;
        }
        __syncthreads();
        if (tidb < 55) {
            int tt = tidb, i = 0;
            while (tt >= DL_ - i) { tt -= DL_ - i; i++; }
            const int j = i + tt;
            g_P[rk * 56 + tidb] = G[i * DL_ + j] * (i == j ? 1.0f : 2.0f);
        }
    } else if (b < 248) {               // ---- upack1 ----
        const int idx = b - 144;
        const int r = idx / 13, tile = idx % 13;
        for (int e = tidb; e < 512; e += 256) {
            const int lane = e & 31, kb = e >> 5;
            const int g = lane >> 2, tig = lane & 3;
            const int j = tile * 8 + g, k0 = kb * 16 + tig * 4;
            uint4 v = make_uint4(0u, 0u, 0u, 0u);
            if (j < 100) {
                const float* up = Us + ((size_t)(r * 10 + j / 10) * D_ + k0) * 10 + (j % 10);
                v.x = tf32b(up[0]);  v.y = tf32b(up[10]);
                v.z = tf32b(up[20]); v.w = tf32b(up[30]);
            }
            ((uint4*)g_u1)[((r * 13 + tile) * 16 + kb) * 32 + lane] = v;
        }
    } else {                            // ---- upack2 ----
        const int idx = b - 248;
        const int r = idx >> 5, tile = idx & 31;
        if (tidb < 224) {
            const int lane = tidb & 31, kb = tidb >> 5;
            const int g = lane >> 2, tig = lane & 3;
            const int dd = tile * 8 + g, j0 = kb * 16 + tig * 4;
            unsigned w[4];
            #pragma unroll
            for (int q = 0; q < 4; q++) {
                const int j = j0 + q;
                w[q] = (j < 100)
                    ? tf32b(Us[((size_t)(r * 10 + j / 10) * D_ + dd) * 10 + (j % 10)])
                    : 0u;
            }
            ((uint4*)g_u2)[((r * 32 + tile) * 7 + kb) * 32 + lane] =
                make_uint4(w[0], w[1], w[2], w[3]);
        }
    }
}

// ---------------- smem layout (bytes) ----------------
#define SM_W   0          // 64 x 512B  w fragments (phase-2 A operand)
#define SM_ZW  32768      // 64 x 104 x 4 = 26624
#define SM_GP  59392      // 2240
#define SM_LG  61632      // 2560
#define SM_LG2 64192      // 2560
#define SMEM_TOTAL 66752  // epilogue bounce (64 x 260 x 4 = 66560) overlays from 0

// ---------------- main fused kernel ----------------
extern "C" __global__ void __launch_bounds__(256, 2)
ks_main(float* __restrict__ out) {
    extern __shared__ __align__(128) char smem[];
    const int tid = threadIdx.x, wid = tid >> 5, lane = tid & 31;
    const int g = lane >> 2, tig = lane & 3;
    const int r = blockIdx.y, tile = blockIdx.x, b0 = tile * MT;
    const int mw = wid >> 2, nw = wid & 3;
    const unsigned sxb = (unsigned)((g & 1) << 6);

    float* ZW  = (float*)(smem + SM_ZW);
    float* GP  = (float*)(smem + SM_GP);
    float* LG  = (float*)(smem + SM_LG);
    float* LG2 = (float*)(smem + SM_LG2);

    for (int i = tid; i < 560; i += 256) GP[i] = g_P[r * 560 + i];

    // ======== GEMM1: z[64][100] = x[64][256] @ Ucat  (pure LDG + HMMA) ========
    {
        const uint4* XP = (const uint4*)g_xp + (size_t)tile * 4096
                        + (tig * 64 + mw * 32 + g);
        const uint4* U1b[4];
        int tv[4];
        #pragma unroll
        for (int nt = 0; nt < 4; nt++) {
            const int t13 = nw + 4 * nt;
            tv[nt] = t13 < 13;
            U1b[nt] = (const uint4*)g_u1 + ((size_t)(r * 13 + (tv[nt] ? t13 : 0)) * 16) * 32 + lane;
        }

        float acc[2][4][4];
        #pragma unroll
        for (int mt = 0; mt < 2; mt++)
            #pragma unroll
            for (int nt = 0; nt < 4; nt++)
                #pragma unroll
                for (int q = 0; q < 4; q++) acc[mt][nt][q] = 0.0f;

        #pragma unroll 4
        for (int kb = 0; kb < 16; kb++) {
            uint4 a[2][2];
            #pragma unroll
            for (int mt = 0; mt < 2; mt++)
                #pragma unroll
                for (int h = 0; h < 2; h++)
                    a[mt][h] = XP[kb * 256 + mt * 16 + 8 * h];
            #pragma unroll
            for (int nt = 0; nt < 4; nt++) {
                if (!tv[nt]) continue;
                const uint4 b = U1b[nt][kb * 32];
                #pragma unroll
                for (int mt = 0; mt < 2; mt++) {
                    mma8(acc[mt][nt], a[mt][0].x, a[mt][1].x, a[mt][0].y, a[mt][1].y, b.x, b.y);
                    mma8(acc[mt][nt], a[mt][0].z, a[mt][1].z, a[mt][0].w, a[mt][1].w, b.z, b.w);
                }
            }
        }
        #pragma unroll
        for (int mt = 0; mt < 2; mt++)
            #pragma unroll
            for (int nt = 0; nt < 4; nt++)
                if (tv[nt]) {
                    const int col = (nw + 4 * nt) * 8 + 2 * tig;
                    const int r0 = mw * 32 + mt * 16 + g;
                    *(float2*)(ZW + r0 * ZSTR + col) = make_float2(acc[mt][nt][0], acc[mt][nt][1]);
                    *(float2*)(ZW + (r0 + 8) * ZSTR + col) = make_float2(acc[mt][nt][2], acc[mt][nt][3]);
                }
    }
    __syncthreads();

    // ======== logits = 10|z_k|^2 - 5 z_k^T G_k z_k ========
    for (int t = tid; t < MT * K_; t += 256) {
        const int row = t / 10, k = t - row * 10;
        const float* zb = ZW + row * ZSTR + k * 10;
        float z[DL_];
        #pragma unroll
        for (int i = 0; i < DL_; i++) z[i] = zb[i];
        float s1 = 0.0f;
        #pragma unroll
        for (int i = 0; i < DL_; i++) s1 += z[i] * z[i];
        const float* Pk = GP + k * 56;
        float s2 = 0.0f; int tt = 0;
        #pragma unroll
        for (int i = 0; i < DL_; i++)
            #pragma unroll
            for (int j = i; j < DL_; j++) { s2 += Pk[tt] * z[i] * z[j]; tt++; }
        LG[t] = 10.0f * s1 - 5.0f * s2;
    }
    __syncthreads();

    // ======== softmax probs (one thread per row) ========
    if (tid < MT) {
        const int row = tid;
        float a[K_], m = -1e30f;
        #pragma unroll
        for (int k = 0; k < K_; k++) { a[k] = LG[row * 10 + k]; m = fmaxf(m, a[k]); }
        float s = 0.0f;
        #pragma unroll
        for (int k = 0; k < K_; k++) { a[k] = expf(a[k] - m); s += a[k]; }
        const float inv = 1.0f / s;
        #pragma unroll
        for (int k = 0; k < K_; k++) LG2[row * 10 + k] = a[k] * inv;
    }
    __syncthreads();

    // ======== w = c*z -> tf32 fragment rows (512B, swizzled) ========
    for (int t = tid; t < MT * 100; t += 256) {
        const int row = t / 100, j = t - row * 100;
        const float wv = LG2[row * 10 + j / 10] * ZW[row * ZSTR + j];
        *(unsigned*)(smem + SM_W + row * 512 +
                     (((unsigned)(j * 4)) ^ ((unsigned)(row & 1) << 6))) = tf32b(wv);
    }
    for (int t = tid; t < MT * 12; t += 256) {   // zero-pad cols 100..111
        const int row = t / 12, j = 100 + (t - row * 12);
        *(unsigned*)(smem + SM_W + row * 512 +
                     (((unsigned)(j * 4)) ^ ((unsigned)(row & 1) << 6))) = 0u;
    }
    __syncthreads();

    // ======== GEMM2: out[64][256] = w[64][112] @ Ucat^T ========
    float acc2[2][8][4];
    {
        #pragma unroll
        for (int mt = 0; mt < 2; mt++)
            #pragma unroll
            for (int nt = 0; nt < 8; nt++)
                #pragma unroll
                for (int q = 0; q < 4; q++) acc2[mt][nt][q] = 0.0f;

        const char* Ar[2][2];
        #pragma unroll
        for (int mt = 0; mt < 2; mt++)
            #pragma unroll
            for (int h = 0; h < 2; h++)
                Ar[mt][h] = smem + SM_W + (mw * 32 + mt * 16 + g + 8 * h) * 512;

        const uint4* U2 = (const uint4*)g_u2 + (size_t)r * (32 * 7 * 32)
                        + (nw * 8) * (7 * 32) + lane;

        #pragma unroll 2
        for (int kb = 0; kb < 7; kb++) {
            const unsigned ka = ((unsigned)(kb * 64 + tig * 16)) ^ sxb;
            uint4 a[2][2];
            #pragma unroll
            for (int mt = 0; mt < 2; mt++)
                #pragma unroll
                for (int h = 0; h < 2; h++)
                    a[mt][h] = *(const uint4*)(Ar[mt][h] + ka);
            #pragma unroll
            for (int nt = 0; nt < 8; nt++) {
                const uint4 b = U2[(nt * 7 + kb) * 32];
                #pragma unroll
                for (int mt = 0; mt < 2; mt++) {
                    mma8(acc2[mt][nt], a[mt][0].x, a[mt][1].x, a[mt][0].y, a[mt][1].y, b.x, b.y);
                    mma8(acc2[mt][nt], a[mt][0].z, a[mt][1].z, a[mt][0].w, a[mt][1].w, b.z, b.w);
                }
            }
        }
    }
    __syncthreads();   // smem reads done; reuse as epilogue bounce

    // ======== epilogue: frags -> smem bounce -> coalesced STG ========
    float* OB = (float*)smem;
    #pragma unroll
    for (int mt = 0; mt < 2; mt++)
        #pragma unroll
        for (int nt = 0; nt < 8; nt++) {
            const int col = (nw * 8 + nt) * 8 + 2 * tig;
            const int r0 = mw * 32 + mt * 16 + g;
            *(float2*)(OB + r0 * OSTR + col) = make_float2(acc2[mt][nt][0], acc2[mt][nt][1]);
            *(float2*)(OB + (r0 + 8) * OSTR + col) = make_float2(acc2[mt][nt][2], acc2[mt][nt][3]);
        }
    __syncthreads();
    for (int i = tid; i < MT * 64; i += 256) {
        const int row = i >> 6, c4 = i & 63;
        const float4 v = *(const float4*)(OB + row * OSTR + c4 * 4);
        *(float4*)(out + ((size_t)r * B_ + b0 + row) * D_ + c4 * 4) = v;
    }
}

extern "C" void kernel_launch(void* const* d_in, const int* in_sizes, int n_in,
                              void* d_out, int out_size) {
    const float* x  = (const float*)d_in[0];   // (4096, 256)
    const float* Us = (const float*)d_in[1];   // (8, 10, 256, 10)
    float* out = (float*)d_out;                // (8, 4096, 256)

    cudaFuncSetAttribute(ks_main, cudaFuncAttributeMaxDynamicSharedMemorySize,
                         SMEM_TOTAL);

    ks_prep<<<504, 256>>>(x, Us);

    dim3 grid(NT_, R_);
    ks_main<<<grid, 256, SMEM_TOTAL>>>(out);
}

// round 6
// speedup vs baseline: 1.8475x; 1.0575x over previous
#include <cuda_runtime.h>

#define R_ 8
#define K_ 10
#define D_ 256
#define DL_ 10
#define B_ 4096
#define MT 64
#define NT_ 64          // number of row tiles = B_/MT
#define ZSTR 132        // 132 mod 32 = 4 -> conflict-friendly; k-slots of 12 floats
#define OSTR 260

// ---------------- device scratch (static, no allocs) ----------------
__device__ float    g_P[R_ * K_ * 56];                 // packed symmetric Gram
__device__ unsigned g_xp[NT_ * 16 * 4 * 64 * 4];       // x tf32 frag-order [tile][kb][tig][row]{4k}  (4MB)
__device__ unsigned g_u1[R_ * 13 * 16 * 32 * 4];       // GEMM1 B frags [r][tile13][kb16][lane]{4k}   (1MB)
__device__ unsigned g_u2[R_ * 32 * 7 * 32 * 4];        // GEMM2 B frags [r][tileN32][kb7][lane]{4j}   (0.9MB)

__device__ __forceinline__ unsigned tf32b(float f) {
    unsigned u;
    asm("cvt.rna.tf32.f32 %0, %1;" : "=r"(u) : "f"(f));
    return u;
}
__device__ __forceinline__ void mma8(float* c, unsigned a0, unsigned a1,
                                     unsigned a2, unsigned a3,
                                     unsigned b0, unsigned b1) {
    asm volatile(
        "mma.sync.aligned.m16n8k8.row.col.f32.tf32.tf32.f32 "
        "{%0,%1,%2,%3}, {%4,%5,%6,%7}, {%8,%9}, {%0,%1,%2,%3};"
        : "+f"(c[0]), "+f"(c[1]), "+f"(c[2]), "+f"(c[3])
        : "r"(a0), "r"(a1), "r"(a2), "r"(a3), "r"(b0), "r"(b1));
}

// ---------------- fused prep kernel ----------------
// blocks [0,64):   xpack tile = b
// blocks [64,144): gram  rk   = b-64
// blocks [144,248): upack1 idx = b-144  (r*13+tile)
// blocks [248,504): upack2 idx = b-248  (r*32+tile)
__global__ void __launch_bounds__(256)
ks_prep(const float* __restrict__ x, const float* __restrict__ Us) {
    const int b = blockIdx.x, tidb = threadIdx.x;

    if (b < 64) {                       // ---- xpack ----
        const int tile = b;
        for (int e = tidb; e < 4096; e += 256) {
            const int row = e & 63, kt = e >> 6;
            const int k0 = (kt >> 2) * 16 + (kt & 3) * 4;
            const float* xp = x + (size_t)(tile * 64 + row) * D_ + k0;
            uint4 v;
            v.x = tf32b(xp[0]); v.y = tf32b(xp[1]);
            v.z = tf32b(xp[2]); v.w = tf32b(xp[3]);
            ((uint4*)g_xp)[(size_t)tile * 4096 + e] = v;
        }
    } else if (b < 144) {               // ---- gram ----
        __shared__ float u[D_ * DL_];
        __shared__ float G[DL_ * DL_];
        const int rk = b - 64;
        const float* Up = Us + (size_t)rk * D_ * DL_;
        for (int i = tidb; i < D_ * DL_; i += 256) u[i] = Up[i];
        __syncthreads();
        if (tidb < DL_ * DL_) {
            const int i = tidb / DL_, j = tidb % DL_;
            float s = 0.0f;
            #pragma unroll 8
            for (int dd = 0; dd < D_; dd++) s += u[dd * DL_ + i] * u[dd * DL_ + j];
            G[tidb] = s;
        }
        __syncthreads();
        if (tidb < 55) {
            int tt = tidb, i = 0;
            while (tt >= DL_ - i) { tt -= DL_ - i; i++; }
            const int j = i + tt;
            g_P[rk * 56 + tidb] = G[i * DL_ + j] * (i == j ? 1.0f : 2.0f);
        }
    } else if (b < 248) {               // ---- upack1 ----
        const int idx = b - 144;
        const int r = idx / 13, tile = idx % 13;
        for (int e = tidb; e < 512; e += 256) {
            const int lane = e & 31, kb = e >> 5;
            const int g = lane >> 2, tig = lane & 3;
            const int j = tile * 8 + g, k0 = kb * 16 + tig * 4;
            uint4 v = make_uint4(0u, 0u, 0u, 0u);
            if (j < 100) {
                const float* up = Us + ((size_t)(r * 10 + j / 10) * D_ + k0) * 10 + (j % 10);
                v.x = tf32b(up[0]);  v.y = tf32b(up[10]);
                v.z = tf32b(up[20]); v.w = tf32b(up[30]);
            }
            ((uint4*)g_u1)[((r * 13 + tile) * 16 + kb) * 32 + lane] = v;
        }
    } else {                            // ---- upack2 ----
        const int idx = b - 248;
        const int r = idx >> 5, tile = idx & 31;
        if (tidb < 224) {
            const int lane = tidb & 31, kb = tidb >> 5;
            const int g = lane >> 2, tig = lane & 3;
            const int dd = tile * 8 + g, j0 = kb * 16 + tig * 4;
            unsigned w[4];
            #pragma unroll
            for (int q = 0; q < 4; q++) {
                const int j = j0 + q;
                w[q] = (j < 100)
                    ? tf32b(Us[((size_t)(r * 10 + j / 10) * D_ + dd) * 10 + (j % 10)])
                    : 0u;
            }
            ((uint4*)g_u2)[((r * 32 + tile) * 7 + kb) * 32 + lane] =
                make_uint4(w[0], w[1], w[2], w[3]);
        }
    }
}

// ---------------- smem layout (bytes) ----------------
#define SM_W   0          // 64 x 512B  w fragments (phase-2 A operand)
#define SM_ZW  32768      // 64 x 132 x 4 = 33792
#define SM_GP  66560      // 2240
#define SM_LG  68800      // 2560
#define SM_LG2 71360      // 2560
#define SMEM_TOTAL 73920  // epilogue bounce (64 x 260 x 4 = 66560) overlays from 0

// ---------------- main fused kernel ----------------
extern "C" __global__ void __launch_bounds__(256, 2)
ks_main(float* __restrict__ out) {
    extern __shared__ __align__(128) char smem[];
    const int tid = threadIdx.x, wid = tid >> 5, lane = tid & 31;
    const int g = lane >> 2, tig = lane & 3;
    const int r = blockIdx.y, tile = blockIdx.x, b0 = tile * MT;
    const int mw = wid >> 2, nw = wid & 3;
    const unsigned sxb = (unsigned)((g & 1) << 6);

    float* ZW  = (float*)(smem + SM_ZW);
    float* GP  = (float*)(smem + SM_GP);
    float* LG  = (float*)(smem + SM_LG);
    float* LG2 = (float*)(smem + SM_LG2);

    for (int i = tid; i < 560; i += 256) GP[i] = g_P[r * 560 + i];

    // ======== GEMM1: z[64][100] = x[64][256] @ Ucat  (double-buffered LDG + HMMA) ========
    {
        const uint4* XP = (const uint4*)g_xp + (size_t)tile * 4096
                        + (tig * 64 + mw * 32 + g);
        const uint4* U1b[4];
        int tv[4];
        #pragma unroll
        for (int nt = 0; nt < 4; nt++) {
            const int t13 = nw + 4 * nt;
            tv[nt] = t13 < 13;
            U1b[nt] = (const uint4*)g_u1 + ((size_t)(r * 13 + (tv[nt] ? t13 : 0)) * 16) * 32 + lane;
        }

        float acc[2][4][4];
        #pragma unroll
        for (int mt = 0; mt < 2; mt++)
            #pragma unroll
            for (int nt = 0; nt < 4; nt++)
                #pragma unroll
                for (int q = 0; q < 4; q++) acc[mt][nt][q] = 0.0f;

        uint4 aa[2][2][2], bb[2][4];
        #pragma unroll
        for (int mt = 0; mt < 2; mt++)
            #pragma unroll
            for (int h = 0; h < 2; h++)
                aa[0][mt][h] = XP[mt * 16 + 8 * h];
        #pragma unroll
        for (int nt = 0; nt < 4; nt++)
            if (tv[nt]) bb[0][nt] = U1b[nt][0];

        #pragma unroll
        for (int kb = 0; kb < 16; kb++) {
            const int cur = kb & 1, nxt = cur ^ 1;
            if (kb < 15) {
                #pragma unroll
                for (int mt = 0; mt < 2; mt++)
                    #pragma unroll
                    for (int h = 0; h < 2; h++)
                        aa[nxt][mt][h] = XP[(kb + 1) * 256 + mt * 16 + 8 * h];
                #pragma unroll
                for (int nt = 0; nt < 4; nt++)
                    if (tv[nt]) bb[nxt][nt] = U1b[nt][(kb + 1) * 32];
            }
            #pragma unroll
            for (int nt = 0; nt < 4; nt++) {
                if (!tv[nt]) continue;
                #pragma unroll
                for (int mt = 0; mt < 2; mt++) {
                    mma8(acc[mt][nt], aa[cur][mt][0].x, aa[cur][mt][1].x,
                         aa[cur][mt][0].y, aa[cur][mt][1].y, bb[cur][nt].x, bb[cur][nt].y);
                    mma8(acc[mt][nt], aa[cur][mt][0].z, aa[cur][mt][1].z,
                         aa[cur][mt][0].w, aa[cur][mt][1].w, bb[cur][nt].z, bb[cur][nt].w);
                }
            }
        }
        #pragma unroll
        for (int mt = 0; mt < 2; mt++)
            #pragma unroll
            for (int nt = 0; nt < 4; nt++)
                if (tv[nt]) {
                    const int col = (nw + 4 * nt) * 8 + 2 * tig;   // even
                    const int ks = col / 10, d = col - ks * 10;    // d even, d+1 <= 9
                    const int r0 = mw * 32 + mt * 16 + g;
                    *(float2*)(ZW + r0 * ZSTR + ks * 12 + d) =
                        make_float2(acc[mt][nt][0], acc[mt][nt][1]);
                    *(float2*)(ZW + (r0 + 8) * ZSTR + ks * 12 + d) =
                        make_float2(acc[mt][nt][2], acc[mt][nt][3]);
                }
    }
    __syncthreads();

    // ======== logits = 10|z_k|^2 - 5 z_k^T G_k z_k  (warp-uniform k) ========
    #pragma unroll
    for (int it = 0; it < 3; it++) {
        const int t = it * 256 + tid;
        if (t < MT * K_) {
            const int row = t & 63, k = t >> 6;          // k uniform within warp
            const float* zb = ZW + row * ZSTR + k * 12;
            const float4 z0 = *(const float4*)zb;
            const float4 z1 = *(const float4*)(zb + 4);
            const float2 z2 = *(const float2*)(zb + 8);
            float z[DL_] = {z0.x, z0.y, z0.z, z0.w, z1.x, z1.y, z1.z, z1.w, z2.x, z2.y};
            float s1 = 0.0f;
            #pragma unroll
            for (int i = 0; i < DL_; i++) s1 += z[i] * z[i];
            const float* Pk = GP + k * 56;               // broadcast loads
            float s2 = 0.0f; int tt = 0;
            #pragma unroll
            for (int i = 0; i < DL_; i++)
                #pragma unroll
                for (int j = i; j < DL_; j++) { s2 += Pk[tt] * z[i] * z[j]; tt++; }
            LG[row * 10 + k] = 10.0f * s1 - 5.0f * s2;
        }
    }
    __syncthreads();

    // ======== softmax probs (one thread per row) ========
    if (tid < MT) {
        const int row = tid;
        float a[K_], m = -1e30f;
        #pragma unroll
        for (int k = 0; k < K_; k++) { a[k] = LG[row * 10 + k]; m = fmaxf(m, a[k]); }
        float s = 0.0f;
        #pragma unroll
        for (int k = 0; k < K_; k++) { a[k] = expf(a[k] - m); s += a[k]; }
        const float inv = 1.0f / s;
        #pragma unroll
        for (int k = 0; k < K_; k++) LG2[row * 10 + k] = a[k] * inv;
    }
    __syncthreads();

    // ======== w = c*z -> tf32 fragment rows (512B, swizzled) ========
    for (int t = tid; t < MT * 100; t += 256) {
        const int row = t / 100, j = t - row * 100;
        const int ks = j / 10, d = j - ks * 10;
        const float wv = LG2[row * 10 + ks] * ZW[row * ZSTR + ks * 12 + d];
        *(unsigned*)(smem + SM_W + row * 512 +
                     (((unsigned)(j * 4)) ^ ((unsigned)(row & 1) << 6))) = tf32b(wv);
    }
    for (int t = tid; t < MT * 12; t += 256) {   // zero-pad cols 100..111
        const int row = t / 12, j = 100 + (t - row * 12);
        *(unsigned*)(smem + SM_W + row * 512 +
                     (((unsigned)(j * 4)) ^ ((unsigned)(row & 1) << 6))) = 0u;
    }
    __syncthreads();

    // ======== GEMM2: out[64][256] = w[64][112] @ Ucat^T ========
    float acc2[2][8][4];
    {
        #pragma unroll
        for (int mt = 0; mt < 2; mt++)
            #pragma unroll
            for (int nt = 0; nt < 8; nt++)
                #pragma unroll
                for (int q = 0; q < 4; q++) acc2[mt][nt][q] = 0.0f;

        const char* Ar[2][2];
        #pragma unroll
        for (int mt = 0; mt < 2; mt++)
            #pragma unroll
            for (int h = 0; h < 2; h++)
                Ar[mt][h] = smem + SM_W + (mw * 32 + mt * 16 + g + 8 * h) * 512;

        const uint4* U2 = (const uint4*)g_u2 + (size_t)r * (32 * 7 * 32)
                        + (nw * 8) * (7 * 32) + lane;

        #pragma unroll 2
        for (int kb = 0; kb < 7; kb++) {
            const unsigned ka = ((unsigned)(kb * 64 + tig * 16)) ^ sxb;
            uint4 a[2][2];
            #pragma unroll
            for (int mt = 0; mt < 2; mt++)
                #pragma unroll
                for (int h = 0; h < 2; h++)
                    a[mt][h] = *(const uint4*)(Ar[mt][h] + ka);
            #pragma unroll
            for (int nt = 0; nt < 8; nt++) {
                const uint4 b = U2[(nt * 7 + kb) * 32];
                #pragma unroll
                for (int mt = 0; mt < 2; mt++) {
                    mma8(acc2[mt][nt], a[mt][0].x, a[mt][1].x, a[mt][0].y, a[mt][1].y, b.x, b.y);
                    mma8(acc2[mt][nt], a[mt][0].z, a[mt][1].z, a[mt][0].w, a[mt][1].w, b.z, b.w);
                }
            }
        }
    }
    __syncthreads();   // smem reads done; reuse as epilogue bounce

    // ======== epilogue: frags -> smem bounce -> coalesced STG ========
    float* OB = (float*)smem;
    #pragma unroll
    for (int mt = 0; mt < 2; mt++)
        #pragma unroll
        for (int nt = 0; nt < 8; nt++) {
            const int col = (nw * 8 + nt) * 8 + 2 * tig;
            const int r0 = mw * 32 + mt * 16 + g;
            *(float2*)(OB + r0 * OSTR + col) = make_float2(acc2[mt][nt][0], acc2[mt][nt][1]);
            *(float2*)(OB + (r0 + 8) * OSTR + col) = make_float2(acc2[mt][nt][2], acc2[mt][nt][3]);
        }
    __syncthreads();
    for (int i = tid; i < MT * 64; i += 256) {
        const int row = i >> 6, c4 = i & 63;
        const float4 v = *(const float4*)(OB + row * OSTR + c4 * 4);
        *(float4*)(out + ((size_t)r * B_ + b0 + row) * D_ + c4 * 4) = v;
    }
}

extern "C" void kernel_launch(void* const* d_in, const int* in_sizes, int n_in,
                              void* d_out, int out_size) {
    const float* x  = (const float*)d_in[0];   // (4096, 256)
    const float* Us = (const float*)d_in[1];   // (8, 10, 256, 10)
    float* out = (float*)d_out;                // (8, 4096, 256)

    cudaFuncSetAttribute(ks_main, cudaFuncAttributeMaxDynamicSharedMemorySize,
                         SMEM_TOTAL);

    ks_prep<<<504, 256>>>(x, Us);

    dim3 grid(NT_, R_);
    ks_main<<<grid, 256, SMEM_TOTAL>>>(out);
}

// round 8
// speedup vs baseline: 2.0547x; 1.1122x over previous
#include <cuda_runtime.h>

#define R_ 8
#define K_ 10
#define D_ 256
#define DL_ 10
#define B_ 4096
#define MT 64
#define NT_ 64          // number of row tiles = B_/MT
#define ZSTR 132        // 132 mod 32 = 4 -> conflict-friendly; k-slots of 12 floats

// ---------------- device scratch (static, no allocs) ----------------
__device__ float    g_P[R_ * K_ * 56];                 // packed symmetric Gram
__device__ unsigned g_xp[NT_ * 16 * 4 * 64 * 4];       // x tf32 frag-order [tile][kb][tig][row]{4k}  (4MB)
__device__ unsigned g_u1[R_ * 13 * 16 * 32 * 4];       // GEMM1 B frags [r][tile13][kb16][lane]{4k}   (1MB)
__device__ unsigned g_u2[R_ * 32 * 7 * 32 * 4];        // GEMM2 B frags [r][tileN32][kb7][lane]{4j}   (0.9MB)

__device__ __forceinline__ unsigned tf32b(float f) {
    unsigned u;
    asm("cvt.rna.tf32.f32 %0, %1;" : "=r"(u) : "f"(f));
    return u;
}
__device__ __forceinline__ void mma8(float* c, unsigned a0, unsigned a1,
                                     unsigned a2, unsigned a3,
                                     unsigned b0, unsigned b1) {
    asm volatile(
        "mma.sync.aligned.m16n8k8.row.col.f32.tf32.tf32.f32 "
        "{%0,%1,%2,%3}, {%4,%5,%6,%7}, {%8,%9}, {%0,%1,%2,%3};"
        : "+f"(c[0]), "+f"(c[1]), "+f"(c[2]), "+f"(c[3])
        : "r"(a0), "r"(a1), "r"(a2), "r"(a3), "r"(b0), "r"(b1));
}

// ---------------- fused prep kernel ----------------
// blocks [0,256):   xpack  tile = b>>2, quarter = b&3
// blocks [256,336): gram   rk   = b-256
// blocks [336,440): upack1 idx  = b-336  (r*13+tile)
// blocks [440,696): upack2 idx  = b-440  (r*32+tile)
__global__ void __launch_bounds__(256)
ks_prep(const float* __restrict__ x, const float* __restrict__ Us) {
    const int b = blockIdx.x, tidb = threadIdx.x;

    if (b < 256) {                      // ---- xpack (quarter tiles) ----
        const int tile = b >> 2, q = b & 3;
        #pragma unroll
        for (int it = 0; it < 4; it++) {
            const int e = q * 1024 + it * 256 + tidb;
            const int row = e & 63, kt = e >> 6;
            const int k0 = (kt >> 2) * 16 + (kt & 3) * 4;
            const float* xp = x + (size_t)(tile * 64 + row) * D_ + k0;
            uint4 v;
            v.x = tf32b(xp[0]); v.y = tf32b(xp[1]);
            v.z = tf32b(xp[2]); v.w = tf32b(xp[3]);
            ((uint4*)g_xp)[(size_t)tile * 4096 + e] = v;
        }
    } else if (b < 336) {               // ---- gram ----
        __shared__ float u[D_ * DL_];
        __shared__ float G[DL_ * DL_];
        const int rk = b - 256;
        const float* Up = Us + (size_t)rk * D_ * DL_;
        for (int i = tidb; i < D_ * DL_; i += 256) u[i] = Up[i];
        __syncthreads();
        if (tidb < DL_ * DL_) {
            const int i = tidb / DL_, j = tidb % DL_;
            float s = 0.0f;
            #pragma unroll 8
            for (int dd = 0; dd < D_; dd++) s += u[dd * DL_ + i] * u[dd * DL_ + j];
            G[tidb] = s;
        }
        __syncthreads();
        if (tidb < 55) {
            int tt = tidb, i = 0;
            while (tt >= DL_ - i) { tt -= DL_ - i; i++; }
            const int j = i + tt;
            g_P[rk * 56 + tidb] = G[i * DL_ + j] * (i == j ? 1.0f : 2.0f);
        }
    } else if (b < 440) {               // ---- upack1 ----
        const int idx = b - 336;
        const int r = idx / 13, tile = idx % 13;
        for (int e = tidb; e < 512; e += 256) {
            const int lane = e & 31, kb = e >> 5;
            const int g = lane >> 2, tig = lane & 3;
            const int j = tile * 8 + g, k0 = kb * 16 + tig * 4;
            uint4 v = make_uint4(0u, 0u, 0u, 0u);
            if (j < 100) {
                const float* up = Us + ((size_t)(r * 10 + j / 10) * D_ + k0) * 10 + (j % 10);
                v.x = tf32b(up[0]);  v.y = tf32b(up[10]);
                v.z = tf32b(up[20]); v.w = tf32b(up[30]);
            }
            ((uint4*)g_u1)[((r * 13 + tile) * 16 + kb) * 32 + lane] = v;
        }
    } else {                            // ---- upack2 ----
        const int idx = b - 440;
        const int r = idx >> 5, tile = idx & 31;
        if (tidb < 224) {
            const int lane = tidb & 31, kb = tidb >> 5;
            const int g = lane >> 2, tig = lane & 3;
            const int dd = tile * 8 + g, j0 = kb * 16 + tig * 4;
            unsigned w[4];
            #pragma unroll
            for (int q = 0; q < 4; q++) {
                const int j = j0 + q;
                w[q] = (j < 100)
                    ? tf32b(Us[((size_t)(r * 10 + j / 10) * D_ + dd) * 10 + (j % 10)])
                    : 0u;
            }
            ((uint4*)g_u2)[((r * 32 + tile) * 7 + kb) * 32 + lane] =
                make_uint4(w[0], w[1], w[2], w[3]);
        }
    }
}

// ---------------- smem layout (bytes) ----------------
#define SM_W   0          // 64 x 512B  w fragments (phase-2 A operand)
#define SM_ZW  32768      // 64 x 132 x 4 = 33792
#define SM_GP  66560      // 2240
#define SM_LG  68800      // 2560
#define SM_LG2 71360      // 2560
#define SMEM_TOTAL 73920

// ---------------- main fused kernel ----------------
extern "C" __global__ void __launch_bounds__(256, 2)
ks_main(float* __restrict__ out) {
    extern __shared__ __align__(128) char smem[];
    const int tid = threadIdx.x, wid = tid >> 5, lane = tid & 31;
    const int g = lane >> 2, tig = lane & 3;
    const int r = blockIdx.y, tile = blockIdx.x, b0 = tile * MT;
    const int mw = wid >> 2, nw = wid & 3;
    const unsigned sxb = (unsigned)((g & 1) << 6);

    float* ZW  = (float*)(smem + SM_ZW);
    float* GP  = (float*)(smem + SM_GP);
    float* LG  = (float*)(smem + SM_LG);
    float* LG2 = (float*)(smem + SM_LG2);

    for (int i = tid; i < 560; i += 256) GP[i] = g_P[r * 560 + i];

    // ======== GEMM1: z[64][100] = x[64][256] @ Ucat  (double-buffered LDG + HMMA) ========
    {
        const uint4* XP = (const uint4*)g_xp + (size_t)tile * 4096
                        + (tig * 64 + mw * 32 + g);
        const uint4* U1b[4];
        int tv[4];
        #pragma unroll
        for (int nt = 0; nt < 4; nt++) {
            const int t13 = nw + 4 * nt;
            tv[nt] = t13 < 13;
            U1b[nt] = (const uint4*)g_u1 + ((size_t)(r * 13 + (tv[nt] ? t13 : 0)) * 16) * 32 + lane;
        }

        float acc[2][4][4];
        #pragma unroll
        for (int mt = 0; mt < 2; mt++)
            #pragma unroll
            for (int nt = 0; nt < 4; nt++)
                #pragma unroll
                for (int q = 0; q < 4; q++) acc[mt][nt][q] = 0.0f;

        uint4 aa[2][2][2], bb[2][4];
        #pragma unroll
        for (int mt = 0; mt < 2; mt++)
            #pragma unroll
            for (int h = 0; h < 2; h++)
                aa[0][mt][h] = XP[mt * 16 + 8 * h];
        #pragma unroll
        for (int nt = 0; nt < 4; nt++)
            if (tv[nt]) bb[0][nt] = U1b[nt][0];

        #pragma unroll
        for (int kb = 0; kb < 16; kb++) {
            const int cur = kb & 1, nxt = cur ^ 1;
            if (kb < 15) {
                #pragma unroll
                for (int mt = 0; mt < 2; mt++)
                    #pragma unroll
                    for (int h = 0; h < 2; h++)
                        aa[nxt][mt][h] = XP[(kb + 1) * 256 + mt * 16 + 8 * h];
                #pragma unroll
                for (int nt = 0; nt < 4; nt++)
                    if (tv[nt]) bb[nxt][nt] = U1b[nt][(kb + 1) * 32];
            }
            #pragma unroll
            for (int nt = 0; nt < 4; nt++) {
                if (!tv[nt]) continue;
                #pragma unroll
                for (int mt = 0; mt < 2; mt++) {
                    mma8(acc[mt][nt], aa[cur][mt][0].x, aa[cur][mt][1].x,
                         aa[cur][mt][0].y, aa[cur][mt][1].y, bb[cur][nt].x, bb[cur][nt].y);
                    mma8(acc[mt][nt], aa[cur][mt][0].z, aa[cur][mt][1].z,
                         aa[cur][mt][0].w, aa[cur][mt][1].w, bb[cur][nt].z, bb[cur][nt].w);
                }
            }
        }
        #pragma unroll
        for (int mt = 0; mt < 2; mt++)
            #pragma unroll
            for (int nt = 0; nt < 4; nt++)
                if (tv[nt]) {
                    const int col = (nw + 4 * nt) * 8 + 2 * tig;   // even
                    const int ks = col / 10, d = col - ks * 10;    // d even, d+1 <= 9
                    const int r0 = mw * 32 + mt * 16 + g;
                    *(float2*)(ZW + r0 * ZSTR + ks * 12 + d) =
                        make_float2(acc[mt][nt][0], acc[mt][nt][1]);
                    *(float2*)(ZW + (r0 + 8) * ZSTR + ks * 12 + d) =
                        make_float2(acc[mt][nt][2], acc[mt][nt][3]);
                }
    }
    __syncthreads();

    // ======== logits = 10|z_k|^2 - 5 z_k^T G_k z_k  (warp-uniform k) ========
    #pragma unroll
    for (int it = 0; it < 3; it++) {
        const int t = it * 256 + tid;
        if (t < MT * K_) {
            const int row = t & 63, k = t >> 6;          // k uniform within warp
            const float* zb = ZW + row * ZSTR + k * 12;
            const float4 z0 = *(const float4*)zb;
            const float4 z1 = *(const float4*)(zb + 4);
            const float2 z2 = *(const float2*)(zb + 8);
            float z[DL_] = {z0.x, z0.y, z0.z, z0.w, z1.x, z1.y, z1.z, z1.w, z2.x, z2.y};
            float s1 = 0.0f;
            #pragma unroll
            for (int i = 0; i < DL_; i++) s1 += z[i] * z[i];
            const float* Pk = GP + k * 56;               // broadcast loads
            float s2 = 0.0f; int tt = 0;
            #pragma unroll
            for (int i = 0; i < DL_; i++)
                #pragma unroll
                for (int j = i; j < DL_; j++) { s2 += Pk[tt] * z[i] * z[j]; tt++; }
            LG[row * 10 + k] = 10.0f * s1 - 5.0f * s2;
        }
    }
    __syncthreads();

    // ======== softmax probs (one thread per row) ========
    if (tid < MT) {
        const int row = tid;
        float a[K_], m = -1e30f;
        #pragma unroll
        for (int k = 0; k < K_; k++) { a[k] = LG[row * 10 + k]; m = fmaxf(m, a[k]); }
        float s = 0.0f;
        #pragma unroll
        for (int k = 0; k < K_; k++) { a[k] = __expf(a[k] - m); s += a[k]; }
        const float inv = 1.0f / s;
        #pragma unroll
        for (int k = 0; k < K_; k++) LG2[row * 10 + k] = a[k] * inv;
    }
    __syncthreads();

    // ======== w = c*z -> tf32 fragment rows (512B, swizzled); division-free ========
    {
        const int row = tid >> 2, sub = tid & 3;
        const float* zrow = ZW + row * ZSTR;
        const float* crow = LG2 + row * 10;
        const unsigned base = SM_W + row * 512;
        const unsigned x6 = ((unsigned)(row & 1)) << 6;
        int j = sub * 25;
        int ks = (5 * sub) >> 1;         // 0,2,5,7
        int d  = (sub & 1) * 5;          // 0,5,0,5
        #pragma unroll
        for (int i = 0; i < 25; i++) {
            const float wv = crow[ks] * zrow[ks * 12 + d];
            *(unsigned*)(smem + base + (((unsigned)(j * 4)) ^ x6)) = tf32b(wv);
            j++; d++;
            if (d == 10) { d = 0; ks++; }
        }
        // zero-pad cols 100..111 (3 per thread)
        #pragma unroll
        for (int i = 0; i < 3; i++) {
            const int jp = 100 + sub * 3 + i;
            *(unsigned*)(smem + base + (((unsigned)(jp * 4)) ^ x6)) = 0u;
        }
    }
    __syncthreads();

    // ======== GEMM2: out[64][256] = w[64][112] @ Ucat^T ========
    float acc2[2][8][4];
    {
        #pragma unroll
        for (int mt = 0; mt < 2; mt++)
            #pragma unroll
            for (int nt = 0; nt < 8; nt++)
                #pragma unroll
                for (int q = 0; q < 4; q++) acc2[mt][nt][q] = 0.0f;

        const char* Ar[2][2];
        #pragma unroll
        for (int mt = 0; mt < 2; mt++)
            #pragma unroll
            for (int h = 0; h < 2; h++)
                Ar[mt][h] = smem + SM_W + (mw * 32 + mt * 16 + g + 8 * h) * 512;

        const uint4* U2 = (const uint4*)g_u2 + (size_t)r * (32 * 7 * 32)
                        + (nw * 8) * (7 * 32) + lane;

        #pragma unroll 2
        for (int kb = 0; kb < 7; kb++) {
            const unsigned ka = ((unsigned)(kb * 64 + tig * 16)) ^ sxb;
            uint4 a[2][2];
            #pragma unroll
            for (int mt = 0; mt < 2; mt++)
                #pragma unroll
                for (int h = 0; h < 2; h++)
                    a[mt][h] = *(const uint4*)(Ar[mt][h] + ka);
            #pragma unroll
            for (int nt = 0; nt < 8; nt++) {
                const uint4 b = U2[(nt * 7 + kb) * 32];
                #pragma unroll
                for (int mt = 0; mt < 2; mt++) {
                    mma8(acc2[mt][nt], a[mt][0].x, a[mt][1].x, a[mt][0].y, a[mt][1].y, b.x, b.y);
                    mma8(acc2[mt][nt], a[mt][0].z, a[mt][1].z, a[mt][0].w, a[mt][1].w, b.z, b.w);
                }
            }
        }
    }

    // ======== epilogue: direct STG.64 from fragments (32B chunks per quad) ========
    {
        float* op = out + ((size_t)r * B_ + b0) * D_;
        #pragma unroll
        for (int mt = 0; mt < 2; mt++) {
            const int r0 = mw * 32 + mt * 16 + g;
            #pragma unroll
            for (int nt = 0; nt < 8; nt++) {
                const int col = (nw * 8 + nt) * 8 + 2 * tig;
                *(float2*)(op + r0 * D_ + col) =
                    make_float2(acc2[mt][nt][0], acc2[mt][nt][1]);
                *(float2*)(op + (r0 + 8) * D_ + col) =
                    make_float2(acc2[mt][nt][2], acc2[mt][nt][3]);
            }
        }
    }
}

extern "C" void kernel_launch(void* const* d_in, const int* in_sizes, int n_in,
                              void* d_out, int out_size) {
    const float* x  = (const float*)d_in[0];   // (4096, 256)
    const float* Us = (const float*)d_in[1];   // (8, 10, 256, 10)
    float* out = (float*)d_out;                // (8, 4096, 256)

    cudaFuncSetAttribute(ks_main, cudaFuncAttributeMaxDynamicSharedMemorySize,
                         SMEM_TOTAL);

    ks_prep<<<696, 256>>>(x, Us);

    dim3 grid(NT_, R_);
    ks_main<<<grid, 256, SMEM_TOTAL>>>(out);
}

// round 9
// speedup vs baseline: 2.2579x; 1.0989x over previous
#include <cuda_runtime.h>

#define R_ 8
#define K_ 10
#define D_ 256
#define DL_ 10
#define B_ 4096
#define MT 64
#define NT_ 64          // number of row tiles = B_/MT
#define ZSTR 132        // 132 mod 32 = 4 -> conflict-friendly; k-slots of 12 floats

// ---------------- device scratch (static, no allocs) ----------------
__device__ float    g_P[R_ * K_ * 56];                 // packed symmetric Gram
__device__ unsigned g_xp[NT_ * 16 * 4 * 64 * 4];       // x tf32 frag-order [tile][kb][tig][row]{4k}  (4MB)
__device__ unsigned g_u1[R_ * 13 * 16 * 32 * 4];       // GEMM1 B frags [r][tile13][kb16][lane]{4k}   (1MB)
__device__ unsigned g_u2[R_ * 32 * 7 * 32 * 4];        // GEMM2 B frags [r][tileN32][kb7][lane]{4j}   (0.9MB)

__device__ __forceinline__ unsigned tf32b(float f) {
    unsigned u;
    asm("cvt.rna.tf32.f32 %0, %1;" : "=r"(u) : "f"(f));
    return u;
}
__device__ __forceinline__ void mma8(float* c, unsigned a0, unsigned a1,
                                     unsigned a2, unsigned a3,
                                     unsigned b0, unsigned b1) {
    asm volatile(
        "mma.sync.aligned.m16n8k8.row.col.f32.tf32.tf32.f32 "
        "{%0,%1,%2,%3}, {%4,%5,%6,%7}, {%8,%9}, {%0,%1,%2,%3};"
        : "+f"(c[0]), "+f"(c[1]), "+f"(c[2]), "+f"(c[3])
        : "r"(a0), "r"(a1), "r"(a2), "r"(a3), "r"(b0), "r"(b1));
}

// ---------------- fused prep kernel ----------------
// blocks [0,256):   xpack  tile = b>>2, quarter = b&3
// blocks [256,336): gram   rk   = b-256
// blocks [336,440): upack1 idx  = b-336  (r*13+tile)
// blocks [440,696): upack2 idx  = b-440  (r*32+tile)
__global__ void __launch_bounds__(256)
ks_prep(const float* __restrict__ x, const float* __restrict__ Us) {
    const int b = blockIdx.x, tidb = threadIdx.x;

    if (b < 256) {                      // ---- xpack (quarter tiles) ----
        const int tile = b >> 2, q = b & 3;
        #pragma unroll
        for (int it = 0; it < 4; it++) {
            const int e = q * 1024 + it * 256 + tidb;
            const int row = e & 63, kt = e >> 6;
            const int k0 = (kt >> 2) * 16 + (kt & 3) * 4;
            const float* xp = x + (size_t)(tile * 64 + row) * D_ + k0;
            uint4 v;
            v.x = tf32b(xp[0]); v.y = tf32b(xp[1]);
            v.z = tf32b(xp[2]); v.w = tf32b(xp[3]);
            ((uint4*)g_xp)[(size_t)tile * 4096 + e] = v;
        }
    } else if (b < 336) {               // ---- gram ----
        __shared__ float u[D_ * DL_];
        __shared__ float G[DL_ * DL_];
        const int rk = b - 256;
        const float* Up = Us + (size_t)rk * D_ * DL_;
        for (int i = tidb; i < D_ * DL_; i += 256) u[i] = Up[i];
        __syncthreads();
        if (tidb < DL_ * DL_) {
            const int i = tidb / DL_, j = tidb % DL_;
            float s = 0.0f;
            #pragma unroll 8
            for (int dd = 0; dd < D_; dd++) s += u[dd * DL_ + i] * u[dd * DL_ + j];
            G[tidb] = s;
        }
        __syncthreads();
        if (tidb < 55) {
            int tt = tidb, i = 0;
            while (tt >= DL_ - i) { tt -= DL_ - i; i++; }
            const int j = i + tt;
            g_P[rk * 56 + tidb] = G[i * DL_ + j] * (i == j ? 1.0f : 2.0f);
        }
    } else if (b < 440) {               // ---- upack1 ----
        const int idx = b - 336;
        const int r = idx / 13, tile = idx % 13;
        for (int e = tidb; e < 512; e += 256) {
            const int lane = e & 31, kb = e >> 5;
            const int g = lane >> 2, tig = lane & 3;
            const int j = tile * 8 + g, k0 = kb * 16 + tig * 4;
            uint4 v = make_uint4(0u, 0u, 0u, 0u);
            if (j < 100) {
                const float* up = Us + ((size_t)(r * 10 + j / 10) * D_ + k0) * 10 + (j % 10);
                v.x = tf32b(up[0]);  v.y = tf32b(up[10]);
                v.z = tf32b(up[20]); v.w = tf32b(up[30]);
            }
            ((uint4*)g_u1)[((r * 13 + tile) * 16 + kb) * 32 + lane] = v;
        }
    } else {                            // ---- upack2 ----
        const int idx = b - 440;
        const int r = idx >> 5, tile = idx & 31;
        if (tidb < 224) {
            const int lane = tidb & 31, kb = tidb >> 5;
            const int g = lane >> 2, tig = lane & 3;
            const int dd = tile * 8 + g, j0 = kb * 16 + tig * 4;
            unsigned w[4];
            #pragma unroll
            for (int q = 0; q < 4; q++) {
                const int j = j0 + q;
                w[q] = (j < 100)
                    ? tf32b(Us[((size_t)(r * 10 + j / 10) * D_ + dd) * 10 + (j % 10)])
                    : 0u;
            }
            ((uint4*)g_u2)[((r * 32 + tile) * 7 + kb) * 32 + lane] =
                make_uint4(w[0], w[1], w[2], w[3]);
        }
    }
}

// ---------------- smem layout (bytes) ----------------
#define SM_W    0          // 64 x 512B  w fragments (phase-2 A operand)
#define SM_ZWA  32768      // 64 x 132 x 4 = 33792  (K-half 0 partials)
#define SM_ZWB  66560      // 33792                 (K-half 1 partials)
#define SM_GP   100352     // 2240
#define SMEM_TOTAL 102592

// ---------------- main fused kernel ----------------
extern "C" __global__ void __launch_bounds__(256, 2)
ks_main(float* __restrict__ out) {
    extern __shared__ __align__(128) char smem[];
    const int tid = threadIdx.x, wid = tid >> 5, lane = tid & 31;
    const int g = lane >> 2, tig = lane & 3;
    const int r = blockIdx.y, tile = blockIdx.x, b0 = tile * MT;
    const int mw = wid >> 2;            // GEMM1 + GEMM2 m-group
    const int nw = wid & 3;             // GEMM2 n-group
    const int kw = wid & 1;             // GEMM1 k-half
    const int nq = (wid >> 1) & 1;      // GEMM1 n-half
    const unsigned sxb = (unsigned)((g & 1) << 6);

    float* ZWA = (float*)(smem + SM_ZWA);
    float* ZWB = (float*)(smem + SM_ZWB);
    float* GP  = (float*)(smem + SM_GP);

    for (int i = tid; i < 560; i += 256) GP[i] = g_P[r * 560 + i];

    // ======== GEMM1: z[64][100] = x[64][256] @ Ucat  (mw2 x nq2 x kw2 warp grid) ========
    {
        const int ntc = nq ? 6 : 7;                     // tiles: nq=0 -> 0..6, nq=1 -> 7..12
        const uint4* XP = (const uint4*)g_xp + (size_t)tile * 4096
                        + kw * 8 * 256 + tig * 64 + (mw * 32 + g);
        const uint4* U1p = (const uint4*)g_u1
                         + ((size_t)(r * 13 + nq * 7) * 16 + kw * 8) * 32 + lane;

        float acc[2][7][4];
        #pragma unroll
        for (int mt = 0; mt < 2; mt++)
            #pragma unroll
            for (int nt = 0; nt < 7; nt++)
                #pragma unroll
                for (int q = 0; q < 4; q++) acc[mt][nt][q] = 0.0f;

        #pragma unroll
        for (int kb = 0; kb < 8; kb++) {
            uint4 a[2][2];
            #pragma unroll
            for (int mt = 0; mt < 2; mt++)
                #pragma unroll
                for (int h = 0; h < 2; h++)
                    a[mt][h] = XP[kb * 256 + mt * 16 + 8 * h];
            uint4 b[7];
            #pragma unroll
            for (int nt = 0; nt < 7; nt++)
                if (nt < ntc) b[nt] = U1p[nt * 512 + kb * 32];
            #pragma unroll
            for (int nt = 0; nt < 7; nt++) {
                if (nt >= ntc) continue;
                #pragma unroll
                for (int mt = 0; mt < 2; mt++) {
                    mma8(acc[mt][nt], a[mt][0].x, a[mt][1].x, a[mt][0].y, a[mt][1].y,
                         b[nt].x, b[nt].y);
                    mma8(acc[mt][nt], a[mt][0].z, a[mt][1].z, a[mt][0].w, a[mt][1].w,
                         b[nt].z, b[nt].w);
                }
            }
        }
        float* ZWx = kw ? ZWB : ZWA;
        #pragma unroll
        for (int mt = 0; mt < 2; mt++)
            #pragma unroll
            for (int nt = 0; nt < 7; nt++)
                if (nt < ntc) {
                    const int col = (nq * 7 + nt) * 8 + 2 * tig;   // even
                    const int ks = col / 10, d = col - ks * 10;
                    const int r0 = mw * 32 + mt * 16 + g;
                    *(float2*)(ZWx + r0 * ZSTR + ks * 12 + d) =
                        make_float2(acc[mt][nt][0], acc[mt][nt][1]);
                    *(float2*)(ZWx + (r0 + 8) * ZSTR + ks * 12 + d) =
                        make_float2(acc[mt][nt][2], acc[mt][nt][3]);
                }
    }
    __syncthreads();

    // ======== merged: z-sum + logits + softmax (quad shuffles) + w-pack ========
    {
        const int row = tid >> 2, sub = tid & 3;
        const int nk = (sub < 2) ? 3 : 2;        // k = sub, sub+4, sub+8(sub<2)
        const float* zaR = ZWA + row * ZSTR;
        const float* zbR = ZWB + row * ZSTR;

        float z[3][10], lg[3], ex[3];
        float m = -1e30f;
        #pragma unroll
        for (int i = 0; i < 3; i++) {
            if (i >= nk) continue;
            const int k = sub + 4 * i;
            const int base = k * 12;
            const float4 a0 = *(const float4*)(zaR + base);
            const float4 b0 = *(const float4*)(zbR + base);
            const float4 a1 = *(const float4*)(zaR + base + 4);
            const float4 b1 = *(const float4*)(zbR + base + 4);
            const float2 a2 = *(const float2*)(zaR + base + 8);
            const float2 b2 = *(const float2*)(zbR + base + 8);
            z[i][0] = a0.x + b0.x; z[i][1] = a0.y + b0.y;
            z[i][2] = a0.z + b0.z; z[i][3] = a0.w + b0.w;
            z[i][4] = a1.x + b1.x; z[i][5] = a1.y + b1.y;
            z[i][6] = a1.z + b1.z; z[i][7] = a1.w + b1.w;
            z[i][8] = a2.x + b2.x; z[i][9] = a2.y + b2.y;
            float s1 = 0.0f;
            #pragma unroll
            for (int d = 0; d < DL_; d++) s1 += z[i][d] * z[i][d];
            const float* Pk = GP + k * 56;
            float s2 = 0.0f; int tt = 0;
            #pragma unroll
            for (int i2 = 0; i2 < DL_; i2++)
                #pragma unroll
                for (int j2 = i2; j2 < DL_; j2++) { s2 += Pk[tt] * z[i][i2] * z[i][j2]; tt++; }
            lg[i] = 10.0f * s1 - 5.0f * s2;
            m = fmaxf(m, lg[i]);
        }
        m = fmaxf(m, __shfl_xor_sync(0xffffffffu, m, 1));
        m = fmaxf(m, __shfl_xor_sync(0xffffffffu, m, 2));
        float s = 0.0f;
        #pragma unroll
        for (int i = 0; i < 3; i++)
            if (i < nk) { ex[i] = __expf(lg[i] - m); s += ex[i]; }
        s += __shfl_xor_sync(0xffffffffu, s, 1);
        s += __shfl_xor_sync(0xffffffffu, s, 2);
        const float inv = 1.0f / s;

        const unsigned wb = SM_W + row * 512;
        const unsigned x6 = ((unsigned)(row & 1)) << 6;
        #pragma unroll
        for (int i = 0; i < 3; i++) {
            if (i >= nk) continue;
            const int k = sub + 4 * i;
            const float c = ex[i] * inv;
            #pragma unroll
            for (int d = 0; d < DL_; d++) {
                const int j = k * 10 + d;
                *(unsigned*)(smem + wb + (((unsigned)(j * 4)) ^ x6)) = tf32b(c * z[i][d]);
            }
        }
        // zero-pad cols 100..111 (3 per thread)
        #pragma unroll
        for (int i = 0; i < 3; i++) {
            const int jp = 100 + sub * 3 + i;
            *(unsigned*)(smem + wb + (((unsigned)(jp * 4)) ^ x6)) = 0u;
        }
    }
    __syncthreads();

    // ======== GEMM2: out[64][256] = w[64][112] @ Ucat^T ========
    float acc2[2][8][4];
    {
        #pragma unroll
        for (int mt = 0; mt < 2; mt++)
            #pragma unroll
            for (int nt = 0; nt < 8; nt++)
                #pragma unroll
                for (int q = 0; q < 4; q++) acc2[mt][nt][q] = 0.0f;

        const char* Ar[2][2];
        #pragma unroll
        for (int mt = 0; mt < 2; mt++)
            #pragma unroll
            for (int h = 0; h < 2; h++)
                Ar[mt][h] = smem + SM_W + (mw * 32 + mt * 16 + g + 8 * h) * 512;

        const uint4* U2 = (const uint4*)g_u2 + (size_t)r * (32 * 7 * 32)
                        + (nw * 8) * (7 * 32) + lane;

        #pragma unroll 2
        for (int kb = 0; kb < 7; kb++) {
            const unsigned ka = ((unsigned)(kb * 64 + tig * 16)) ^ sxb;
            uint4 a[2][2];
            #pragma unroll
            for (int mt = 0; mt < 2; mt++)
                #pragma unroll
                for (int h = 0; h < 2; h++)
                    a[mt][h] = *(const uint4*)(Ar[mt][h] + ka);
            #pragma unroll
            for (int nt = 0; nt < 8; nt++) {
                const uint4 b = U2[(nt * 7 + kb) * 32];
                #pragma unroll
                for (int mt = 0; mt < 2; mt++) {
                    mma8(acc2[mt][nt], a[mt][0].x, a[mt][1].x, a[mt][0].y, a[mt][1].y, b.x, b.y);
                    mma8(acc2[mt][nt], a[mt][0].z, a[mt][1].z, a[mt][0].w, a[mt][1].w, b.z, b.w);
                }
            }
        }
    }

    // ======== epilogue: direct STG.64 from fragments (32B chunks per quad) ========
    {
        float* op = out + ((size_t)r * B_ + b0) * D_;
        #pragma unroll
        for (int mt = 0; mt < 2; mt++) {
            const int r0 = mw * 32 + mt * 16 + g;
            #pragma unroll
            for (int nt = 0; nt < 8; nt++) {
                const int col = (nw * 8 + nt) * 8 + 2 * tig;
                *(float2*)(op + r0 * D_ + col) =
                    make_float2(acc2[mt][nt][0], acc2[mt][nt][1]);
                *(float2*)(op + (r0 + 8) * D_ + col) =
                    make_float2(acc2[mt][nt][2], acc2[mt][nt][3]);
            }
        }
    }
}

extern "C" void kernel_launch(void* const* d_in, const int* in_sizes, int n_in,
                              void* d_out, int out_size) {
    const float* x  = (const float*)d_in[0];   // (4096, 256)
    const float* Us = (const float*)d_in[1];   // (8, 10, 256, 10)
    float* out = (float*)d_out;                // (8, 4096, 256)

    cudaFuncSetAttribute(ks_main, cudaFuncAttributeMaxDynamicSharedMemorySize,
                         SMEM_TOTAL);

    ks_prep<<<696, 256>>>(x, Us);

    dim3 grid(NT_, R_);
    ks_main<<<grid, 256, SMEM_TOTAL>>>(out);
}